// round 1
// baseline (speedup 1.0000x reference)
#include <cuda_runtime.h>

// ---------------- problem dimensions (fixed by the dataset) ----------------
#define NM    1500
#define ND    800
#define NN    2300          // NM + ND
#define CC    128
#define HH    8
#define HC    1024          // HH*CC
#define EE    80000
#define ETOT  (EE + NN)     // edges + self loops
#define PP    40000         // pos pairs (== neg pairs)
#define NPAIR 80000
#define FDIM  2778
#define D1    1389
#define D2    694
#define D3    463

// ---------------- scratch (static __device__, no allocations) ----------------
__device__ float    g_h    [NN * CC];
__device__ float    g_xl   [NN * HC];
__device__ float    g_xr   [NN * HC];
__device__ float    g_e    [ETOT * HH];
__device__ unsigned g_emax [NN * HH];
__device__ float    g_den  [NN * HH];
__device__ float    g_gat  [NN * HC];
__device__ float    g_cnn  [NN * FDIM];            // fallback cnn buffer
__device__ float    g_feats[(size_t)NPAIR * FDIM];
__device__ float    g_h1   [(size_t)NPAIR * D1];
__device__ float    g_h2   [(size_t)NPAIR * D2];
__device__ float    g_h3   [(size_t)NPAIR * D3];

// ---------------- helpers ----------------
__device__ __forceinline__ unsigned fenc(float f) {
    unsigned u = __float_as_uint(f);
    return (u & 0x80000000u) ? ~u : (u | 0x80000000u);
}
__device__ __forceinline__ float fdec(unsigned u) {
    unsigned v = (u & 0x80000000u) ? (u ^ 0x80000000u) : ~u;
    return __uint_as_float(v);
}

// ---------------- tiled fp32 GEMM: C = act(A[M,K] @ B[K,N] + bias) ----------------
// act: 0 = identity (bias optional), 1 = leaky-relu(slope)
#define BM 128
#define BN 128
#define BKK 8
#define TM 8
#define TN 8

__global__ void __launch_bounds__(256, 2)
sgemm(const float* __restrict__ A, const float* __restrict__ B,
      const float* __restrict__ bias, float* __restrict__ C,
      int M, int N, int K, int act, float slope)
{
    __shared__ float As[BKK][BM];
    __shared__ float Bs[BKK][BN];

    const int tid = threadIdx.x;
    const int m0 = blockIdx.y * BM;
    const int n0 = blockIdx.x * BN;

    const int arow = tid >> 1;            // 0..127
    const int acol = (tid & 1) * 4;       // 0 or 4
    const int brow = tid >> 5;            // 0..7
    const int bcol = (tid & 31) * 4;      // 0..124

    const int tr = (tid >> 4) * TM;       // 0..120
    const int tc = (tid & 15) * TN;       // 0..120

    float acc[TM][TN];
#pragma unroll
    for (int i = 0; i < TM; i++)
#pragma unroll
        for (int j = 0; j < TN; j++) acc[i][j] = 0.f;

    for (int k0 = 0; k0 < K; k0 += BKK) {
#pragma unroll
        for (int j = 0; j < 4; j++) {
            int k = k0 + acol + j;
            int m = m0 + arow;
            As[acol + j][arow] = (m < M && k < K) ? A[(size_t)m * K + k] : 0.f;
        }
#pragma unroll
        for (int j = 0; j < 4; j++) {
            int k = k0 + brow;
            int n = n0 + bcol + j;
            Bs[brow][bcol + j] = (k < K && n < N) ? B[(size_t)k * N + n] : 0.f;
        }
        __syncthreads();

#pragma unroll
        for (int kk = 0; kk < BKK; kk++) {
            float ra[TM], rb[TN];
#pragma unroll
            for (int i = 0; i < TM; i++) ra[i] = As[kk][tr + i];
#pragma unroll
            for (int j = 0; j < TN; j++) rb[j] = Bs[kk][tc + j];
#pragma unroll
            for (int i = 0; i < TM; i++)
#pragma unroll
                for (int j = 0; j < TN; j++) acc[i][j] += ra[i] * rb[j];
        }
        __syncthreads();
    }

#pragma unroll
    for (int i = 0; i < TM; i++) {
        int m = m0 + tr + i;
        if (m >= M) continue;
#pragma unroll
        for (int j = 0; j < TN; j++) {
            int n = n0 + tc + j;
            if (n >= N) continue;
            float v = acc[i][j];
            if (bias) v += bias[n];
            if (act == 1) v = v > 0.f ? v : slope * v;
            C[(size_t)m * N + n] = v;
        }
    }
}

// ---------------- GAT kernels ----------------
__global__ void k_init()
{
    int i = blockIdx.x * blockDim.x + threadIdx.x;
    if (i < NN * HC) g_gat[i] = 0.f;
    if (i < NN * HH) { g_emax[i] = 0u; g_den[i] = 0.f; }
}

__global__ void k_edge_e(const int* __restrict__ ei, const float* __restrict__ att)
{
    int w = (blockIdx.x * blockDim.x + threadIdx.x) >> 5;
    int lane = threadIdx.x & 31;
    if (w >= ETOT) return;
    int s, d;
    if (w < EE) { s = ei[w]; d = ei[EE + w]; } else { s = d = w - EE; }
    const float* xls = g_xl + (size_t)s * HC;
    const float* xrd = g_xr + (size_t)d * HC;
#pragma unroll
    for (int h = 0; h < HH; h++) {
        float sum = 0.f;
#pragma unroll
        for (int c0 = 0; c0 < CC; c0 += 32) {
            int c = c0 + lane;
            float z = xls[h * CC + c] + xrd[h * CC + c];
            z = z > 0.f ? z : 0.2f * z;
            sum += z * __ldg(&att[h * CC + c]);
        }
#pragma unroll
        for (int o = 16; o; o >>= 1) sum += __shfl_down_sync(0xffffffffu, sum, o);
        if (lane == 0) {
            g_e[w * HH + h] = sum;
            atomicMax(&g_emax[d * HH + h], fenc(sum));
        }
    }
}

__global__ void k_exp(const int* __restrict__ ei)
{
    int i = blockIdx.x * blockDim.x + threadIdx.x;
    if (i >= ETOT * HH) return;
    int e = i >> 3, h = i & 7;
    int d = (e < EE) ? ei[EE + e] : e - EE;
    float ex = expf(g_e[i] - fdec(g_emax[d * HH + h]));
    g_e[i] = ex;
    atomicAdd(&g_den[d * HH + h], ex);
}

__global__ void k_aggr(const int* __restrict__ ei)
{
    int e = blockIdx.x;
    int s, d;
    if (e < EE) { s = ei[e]; d = ei[EE + e]; } else { s = d = e - EE; }
    __shared__ float alpha[HH];
    if (threadIdx.x < HH)
        alpha[threadIdx.x] = g_e[e * HH + threadIdx.x] / g_den[d * HH + threadIdx.x];
    __syncthreads();
    const float* xls = g_xl + (size_t)s * HC;
    float* od = g_gat + (size_t)d * HC;
    for (int i = threadIdx.x; i < HC; i += blockDim.x)
        atomicAdd(&od[i], alpha[i >> 7] * xls[i]);
}

// ---------------- CNN over (1, 8, 128) per node ----------------
__global__ void k_conv(const float* __restrict__ gbias,
                       const float* __restrict__ cw1,  const float* __restrict__ cb1,
                       const float* __restrict__ cw4,  const float* __restrict__ cb4,
                       const float* __restrict__ cw16, const float* __restrict__ cb16,
                       const float* __restrict__ cw32, const float* __restrict__ cb32,
                       float* __restrict__ cnn)
{
    __shared__ float row[HC];
    __shared__ float w1[48], w4[192], w16[768], w32[1536];
    __shared__ float b[24];
    int n = blockIdx.x, tid = threadIdx.x;
    for (int i = tid; i < HC; i += blockDim.x)
        row[i] = g_gat[(size_t)n * HC + i] + gbias[i];
    for (int i = tid; i < 48;   i += blockDim.x) w1[i]  = cw1[i];
    for (int i = tid; i < 192;  i += blockDim.x) w4[i]  = cw4[i];
    for (int i = tid; i < 768;  i += blockDim.x) w16[i] = cw16[i];
    for (int i = tid; i < 1536; i += blockDim.x) w32[i] = cw32[i];
    if (tid < 6) { b[tid] = cb1[tid]; b[6+tid] = cb4[tid]; b[12+tid] = cb16[tid]; b[18+tid] = cb32[tid]; }
    __syncthreads();

    float* orow = cnn + (size_t)n * FDIM;
    for (int i = tid; i < FDIM; i += blockDim.x) {
        const float* w; int kw, o, x0, bb, j;
        if (i < 768)       { j = i;        kw = 1;  w = w1;  o = j / 128; x0 = j % 128; bb = 0;  }
        else if (i < 1518) { j = i - 768;  kw = 4;  w = w4;  o = j / 125; x0 = j % 125; bb = 6;  }
        else if (i < 2196) { j = i - 1518; kw = 16; w = w16; o = j / 113; x0 = j % 113; bb = 12; }
        else               { j = i - 2196; kw = 32; w = w32; o = j / 97;  x0 = j % 97;  bb = 18; }
        float s = b[bb + o];
        const float* wo = w + o * 8 * kw;
        for (int kh = 0; kh < 8; kh++)
            for (int x = 0; x < kw; x++)
                s += row[kh * 128 + x0 + x] * wo[kh * kw + x];
        orow[i] = s > 0.f ? s : 0.f;
    }
}

// ---------------- pair features ----------------
__global__ void k_feats(const int* __restrict__ pos, const int* __restrict__ neg,
                        const float* __restrict__ cnn)
{
    int p = blockIdx.x;
    int mi, di;
    if (p < PP) { mi = pos[p * 2]; di = pos[p * 2 + 1]; }
    else        { mi = neg[(p - PP) * 2]; di = neg[(p - PP) * 2 + 1]; }
    const float* a = cnn + (size_t)mi * FDIM;
    const float* bb = cnn + (size_t)(NM + di) * FDIM;
    float* f = g_feats + (size_t)p * FDIM;
    for (int i = threadIdx.x; i < FDIM; i += blockDim.x)
        f[i] = a[i] * bb[i];
}

// ---------------- final GEMV + sigmoid + labels ----------------
__global__ void k_final(const float* __restrict__ mw4, float* __restrict__ out,
                        int write_labels)
{
    int w = (blockIdx.x * blockDim.x + threadIdx.x) >> 5;
    int lane = threadIdx.x & 31;
    if (w >= NPAIR) return;
    const float* hrow = g_h3 + (size_t)w * D3;
    float s = 0.f;
    for (int k = lane; k < D3; k += 32) s += hrow[k] * mw4[k];
#pragma unroll
    for (int o = 16; o; o >>= 1) s += __shfl_down_sync(0xffffffffu, s, o);
    if (lane == 0) {
        out[w] = 1.f / (1.f + expf(-s));
        if (write_labels) out[NPAIR + w] = (w < PP) ? 1.f : 0.f;
    }
}

// ---------------- launcher ----------------
static inline int cdiv(int a, int b) { return (a + b - 1) / b; }

extern "C" void kernel_launch(void* const* d_in, const int* in_sizes, int n_in,
                              void* d_out, int out_size)
{
    const float* mic   = (const float*)d_in[0];
    const float* dis   = (const float*)d_in[1];
    const int*   ei    = (const int*)  d_in[2];
    const int*   pos   = (const int*)  d_in[3];
    const int*   neg   = (const int*)  d_in[4];
    const float* W_mic = (const float*)d_in[6];
    const float* W_dis = (const float*)d_in[7];
    const float* Wl    = (const float*)d_in[8];
    const float* bl    = (const float*)d_in[9];
    const float* Wr    = (const float*)d_in[10];
    const float* br    = (const float*)d_in[11];
    const float* att   = (const float*)d_in[12];
    const float* gbias = (const float*)d_in[13];
    const float* cw1   = (const float*)d_in[14];
    const float* cb1   = (const float*)d_in[15];
    const float* cw4   = (const float*)d_in[16];
    const float* cb4   = (const float*)d_in[17];
    const float* cw16  = (const float*)d_in[18];
    const float* cb16  = (const float*)d_in[19];
    const float* cw32  = (const float*)d_in[20];
    const float* cb32  = (const float*)d_in[21];
    const float* mw1   = (const float*)d_in[22];
    const float* mb1   = (const float*)d_in[23];
    const float* mw2   = (const float*)d_in[24];
    const float* mb2   = (const float*)d_in[25];
    const float* mw3   = (const float*)d_in[26];
    const float* mb3   = (const float*)d_in[27];
    const float* mw4   = (const float*)d_in[28];
    float* out = (float*)d_out;

    float *p_h, *p_xl, *p_xr, *p_feats, *p_h1, *p_h2, *p_cnn;
    cudaGetSymbolAddress((void**)&p_h,     g_h);
    cudaGetSymbolAddress((void**)&p_xl,    g_xl);
    cudaGetSymbolAddress((void**)&p_xr,    g_xr);
    cudaGetSymbolAddress((void**)&p_feats, g_feats);
    cudaGetSymbolAddress((void**)&p_h1,    g_h1);
    cudaGetSymbolAddress((void**)&p_h2,    g_h2);
    cudaGetSymbolAddress((void**)&p_cnn,   g_cnn);
    float* p_h2g; cudaGetSymbolAddress((void**)&p_h2g, g_h2);
    float* p_h3g; cudaGetSymbolAddress((void**)&p_h3g, g_h3);

    // output layout: pred(80000) | labels(80000) | cnn_outputs(2300*2778)
    const int full = 2 * NPAIR + NN * FDIM;
    float* cnn = (out_size >= full) ? (out + 2 * NPAIR) : p_cnn;
    int write_labels = (out_size >= 2 * NPAIR) ? 1 : 0;

    dim3 blk(256);

    // h = concat(mic @ W_mic, dis @ W_dis)
    sgemm<<<dim3(cdiv(CC, BN), cdiv(NM, BM)), blk>>>(mic, W_mic, nullptr, p_h,            NM, CC, NM, 0, 0.f);
    sgemm<<<dim3(cdiv(CC, BN), cdiv(ND, BM)), blk>>>(dis, W_dis, nullptr, p_h + NM * CC,  ND, CC, ND, 0, 0.f);

    // xl / xr
    sgemm<<<dim3(cdiv(HC, BN), cdiv(NN, BM)), blk>>>(p_h, Wl, bl, p_xl, NN, HC, CC, 0, 0.f);
    sgemm<<<dim3(cdiv(HC, BN), cdiv(NN, BM)), blk>>>(p_h, Wr, br, p_xr, NN, HC, CC, 0, 0.f);

    // GAT attention
    k_init<<<cdiv(NN * HC, 256), 256>>>();
    k_edge_e<<<cdiv(ETOT * 32, 256), 256>>>(ei, att);
    k_exp<<<cdiv(ETOT * HH, 256), 256>>>(ei);
    k_aggr<<<ETOT, 256>>>(ei);

    // CNN embeddings
    k_conv<<<NN, 256>>>(gbias, cw1, cb1, cw4, cb4, cw16, cb16, cw32, cb32, cnn);

    // pair features + MLP
    k_feats<<<NPAIR, 256>>>(pos, neg, cnn);
    sgemm<<<dim3(cdiv(D1, BN), cdiv(NPAIR, BM)), blk>>>(p_feats, mw1, mb1, p_h1,  NPAIR, D1, FDIM, 1, 0.01f);
    sgemm<<<dim3(cdiv(D2, BN), cdiv(NPAIR, BM)), blk>>>(p_h1,    mw2, mb2, p_h2g, NPAIR, D2, D1,   1, 0.01f);
    sgemm<<<dim3(cdiv(D3, BN), cdiv(NPAIR, BM)), blk>>>(p_h2g,   mw3, mb3, p_h3g, NPAIR, D3, D2,   1, 0.01f);
    k_final<<<cdiv(NPAIR * 32, 256), 256>>>(mw4, out, write_labels);
}

// round 2
// speedup vs baseline: 3.4291x; 3.4291x over previous
#include <cuda_runtime.h>
#include <cstdint>

// ---------------- problem dimensions (fixed by the dataset) ----------------
#define NM    1500
#define ND    800
#define NN    2300          // NM + ND
#define CC    128
#define HH    8
#define HC    1024          // HH*CC
#define EE    80000
#define ETOT  (EE + NN)     // edges + self loops
#define PP    40000         // pos pairs (== neg pairs)
#define NPAIR 80000
#define FDIM  2778
#define FPAD  2784          // FDIM padded to mult of 32 (16B-aligned rows)
#define D1    1389
#define D1P   1408          // padded
#define D2    694
#define D2P   704
#define D3    463
#define D3P   464

// ---------------- scratch (static __device__, no allocations) ----------------
__device__ float    g_h    [NN * CC];
__device__ float    g_xl   [NN * HC];
__device__ float    g_xr   [NN * HC];
__device__ float    g_e    [ETOT * HH];
__device__ unsigned g_emax [NN * HH];
__device__ float    g_den  [NN * HH];
__device__ float    g_gat  [NN * HC];
__device__ float    g_cnn  [NN * FDIM];            // fallback cnn buffer
__device__ float    g_feats[(size_t)NPAIR * FPAD];
__device__ float    g_h1   [(size_t)NPAIR * D1P];
__device__ float    g_h2   [(size_t)NPAIR * D2P];
__device__ float    g_h3   [(size_t)NPAIR * D3P];
__device__ float    g_w1r  [FPAD * D1];
__device__ float    g_w2r  [D1P * D2];
__device__ float    g_w3r  [D2P * D3];

// ---------------- helpers ----------------
__device__ __forceinline__ unsigned fenc(float f) {
    unsigned u = __float_as_uint(f);
    return (u & 0x80000000u) ? ~u : (u | 0x80000000u);
}
__device__ __forceinline__ float fdec(unsigned u) {
    unsigned v = (u & 0x80000000u) ? (u ^ 0x80000000u) : ~u;
    return __uint_as_float(v);
}
__device__ __forceinline__ float tf32_rna(float v) {
    unsigned u;
    asm("cvt.rna.tf32.f32 %0, %1;" : "=r"(u) : "f"(v));
    return __uint_as_float(u);
}

// ---------------- fp32 tiled GEMM (small feature GEMMs only) ----------------
#define BM 128
#define BN 128
#define BKK 8
#define TM 8
#define TN 8

__global__ void __launch_bounds__(256, 2)
sgemm(const float* __restrict__ A, const float* __restrict__ B,
      const float* __restrict__ bias, float* __restrict__ C,
      int M, int N, int K, int act, float slope)
{
    __shared__ float As[BKK][BM];
    __shared__ float Bs[BKK][BN];

    const int tid = threadIdx.x;
    const int m0 = blockIdx.y * BM;
    const int n0 = blockIdx.x * BN;

    const int arow = tid >> 1;
    const int acol = (tid & 1) * 4;
    const int brow = tid >> 5;
    const int bcol = (tid & 31) * 4;

    const int tr = (tid >> 4) * TM;
    const int tc = (tid & 15) * TN;

    float acc[TM][TN];
#pragma unroll
    for (int i = 0; i < TM; i++)
#pragma unroll
        for (int j = 0; j < TN; j++) acc[i][j] = 0.f;

    for (int k0 = 0; k0 < K; k0 += BKK) {
#pragma unroll
        for (int j = 0; j < 4; j++) {
            int k = k0 + acol + j;
            int m = m0 + arow;
            As[acol + j][arow] = (m < M && k < K) ? A[(size_t)m * K + k] : 0.f;
        }
#pragma unroll
        for (int j = 0; j < 4; j++) {
            int k = k0 + brow;
            int n = n0 + bcol + j;
            Bs[brow][bcol + j] = (k < K && n < N) ? B[(size_t)k * N + n] : 0.f;
        }
        __syncthreads();

#pragma unroll
        for (int kk = 0; kk < BKK; kk++) {
            float ra[TM], rb[TN];
#pragma unroll
            for (int i = 0; i < TM; i++) ra[i] = As[kk][tr + i];
#pragma unroll
            for (int j = 0; j < TN; j++) rb[j] = Bs[kk][tc + j];
#pragma unroll
            for (int i = 0; i < TM; i++)
#pragma unroll
                for (int j = 0; j < TN; j++) acc[i][j] += ra[i] * rb[j];
        }
        __syncthreads();
    }

#pragma unroll
    for (int i = 0; i < TM; i++) {
        int m = m0 + tr + i;
        if (m >= M) continue;
#pragma unroll
        for (int j = 0; j < TN; j++) {
            int n = n0 + tc + j;
            if (n >= N) continue;
            float v = acc[i][j];
            if (bias) v += bias[n];
            if (act == 1) v = v > 0.f ? v : slope * v;
            C[(size_t)m * N + n] = v;
        }
    }
}

// ---------------- tf32 tensor-core GEMM ----------------
// C[M x ldc] = act(A[M x Kp] @ B[Kp x N] + bias), A rows full (M mult of 128).
// A and B must already be tf32-rounded; B rows [Ktrue, Kp) must be zero.
// Block 128x128x32, 8 warps, warp tile 64x32 (m16n8k8 grid 4x4).
#define STAGE_F 8832        // floats per stage: As 128*36 + Bs 32*132
#define SMEM_TC (2 * STAGE_F * 4)

__global__ void __launch_bounds__(256)
gemm_tc(const float* __restrict__ A, const float* __restrict__ B,
        const float* __restrict__ bias, float* __restrict__ C,
        int N, int Kp, int ldc, float slope, int round_out)
{
    extern __shared__ float sm[];
    const int tid  = threadIdx.x;
    const int lane = tid & 31, wid = tid >> 5;
    const int g = lane >> 2, tg = lane & 3;
    const int wm = wid & 1, wn = wid >> 1;          // 2 x 4 warp grid
    const int m0 = blockIdx.y * 128, n0 = blockIdx.x * 128;

    const unsigned smbase = (unsigned)__cvta_generic_to_shared(sm);

    float acc[4][4][4];
#pragma unroll
    for (int a = 0; a < 4; a++)
#pragma unroll
        for (int b = 0; b < 4; b++)
#pragma unroll
            for (int c = 0; c < 4; c++) acc[a][b][c] = 0.f;

    auto fill = [&](int s, int k0) {
        unsigned as = smbase + (unsigned)(s * STAGE_F) * 4u;
        unsigned bs = as + 4608u * 4u;
        // A tile: 128 x 32, rows 16B aligned (Kp mult of 4)
#pragma unroll
        for (int p = 0; p < 4; p++) {
            int i = p * 256 + tid;
            int row = i >> 3, c4 = (i & 7) * 4;
            const float* src = A + (size_t)(m0 + row) * Kp + k0 + c4;
            unsigned d = as + (unsigned)(row * 36 + c4) * 4u;
            asm volatile("cp.async.cg.shared.global [%0], [%1], 16;\n"
                         :: "r"(d), "l"(src));
        }
        // B tile: 32 x 128, scalar cp.async (N odd -> rows not 16B aligned)
#pragma unroll
        for (int p = 0; p < 16; p++) {
            int i = p * 256 + tid;
            int kr = i >> 7, nc = i & 127;
            int gn = n0 + nc;
            int ok = (gn < N) ? 4 : 0;
            const float* src = B + (size_t)(k0 + kr) * N + (gn < N ? gn : 0);
            unsigned d = bs + (unsigned)(kr * 132 + nc) * 4u;
            asm volatile("cp.async.ca.shared.global [%0], [%1], 4, %2;\n"
                         :: "r"(d), "l"(src), "r"(ok));
        }
        asm volatile("cp.async.commit_group;\n");
    };

    const int T = Kp / 32;
    fill(0, 0);
    for (int t = 0; t < T; ++t) {
        if (t + 1 < T) {
            fill((t + 1) & 1, (t + 1) * 32);
            asm volatile("cp.async.wait_group 1;\n");
        } else {
            asm volatile("cp.async.wait_group 0;\n");
        }
        __syncthreads();
        const float* As = sm + (t & 1) * STAGE_F;
        const float* Bs = As + 4608;
#pragma unroll
        for (int kk = 0; kk < 4; ++kk) {
            const int k = kk * 8;
            unsigned a[4][4], b[4][2];
#pragma unroll
            for (int mt = 0; mt < 4; ++mt) {
                int rb = wm * 64 + mt * 16;
                a[mt][0] = __float_as_uint(As[(rb + g)     * 36 + k + tg]);
                a[mt][1] = __float_as_uint(As[(rb + 8 + g) * 36 + k + tg]);
                a[mt][2] = __float_as_uint(As[(rb + g)     * 36 + k + tg + 4]);
                a[mt][3] = __float_as_uint(As[(rb + 8 + g) * 36 + k + tg + 4]);
            }
#pragma unroll
            for (int nt = 0; nt < 4; ++nt) {
                int cb = wn * 32 + nt * 8;
                b[nt][0] = __float_as_uint(Bs[(k + tg)     * 132 + cb + g]);
                b[nt][1] = __float_as_uint(Bs[(k + tg + 4) * 132 + cb + g]);
            }
#pragma unroll
            for (int mt = 0; mt < 4; ++mt)
#pragma unroll
                for (int nt = 0; nt < 4; ++nt)
                    asm volatile(
                        "mma.sync.aligned.m16n8k8.row.col.f32.tf32.tf32.f32 "
                        "{%0,%1,%2,%3}, {%4,%5,%6,%7}, {%8,%9}, {%0,%1,%2,%3};\n"
                        : "+f"(acc[mt][nt][0]), "+f"(acc[mt][nt][1]),
                          "+f"(acc[mt][nt][2]), "+f"(acc[mt][nt][3])
                        : "r"(a[mt][0]), "r"(a[mt][1]), "r"(a[mt][2]), "r"(a[mt][3]),
                          "r"(b[nt][0]), "r"(b[nt][1]));
        }
        __syncthreads();
    }

    // epilogue: bias + leaky-relu + optional tf32 rounding; zero pad cols [N, ldc)
#pragma unroll
    for (int mt = 0; mt < 4; ++mt) {
#pragma unroll
        for (int nt = 0; nt < 4; ++nt) {
            int r0 = m0 + wm * 64 + mt * 16 + g;
            int c0 = n0 + wn * 32 + nt * 8 + 2 * tg;
#pragma unroll
            for (int e = 0; e < 4; ++e) {
                int r = r0 + (e >> 1) * 8;
                int c = c0 + (e & 1);
                if (c < ldc) {
                    float v = 0.f;
                    if (c < N) {
                        v = acc[mt][nt][e] + bias[c];
                        v = v > 0.f ? v : slope * v;
                        if (round_out) v = tf32_rna(v);
                    }
                    C[(size_t)r * ldc + c] = v;
                }
            }
        }
    }
}

// ---------------- weight pre-round (fp32 -> tf32, zero K padding) ----------------
__global__ void k_round(const float* __restrict__ src, float* __restrict__ dst,
                        int Ktrue, int N, int total)
{
    int i = blockIdx.x * blockDim.x + threadIdx.x;
    if (i >= total) return;
    int k = i / N;
    dst[i] = (k < Ktrue) ? tf32_rna(src[i]) : 0.f;
}

// ---------------- GAT kernels ----------------
__global__ void k_init()
{
    int i = blockIdx.x * blockDim.x + threadIdx.x;
    if (i < NN * HC) g_gat[i] = 0.f;
    if (i < NN * HH) { g_emax[i] = 0u; g_den[i] = 0.f; }
}

__global__ void k_edge_e(const int* __restrict__ ei, const float* __restrict__ att)
{
    int w = (blockIdx.x * blockDim.x + threadIdx.x) >> 5;
    int lane = threadIdx.x & 31;
    if (w >= ETOT) return;
    int s, d;
    if (w < EE) { s = ei[w]; d = ei[EE + w]; } else { s = d = w - EE; }
    const float* xls = g_xl + (size_t)s * HC;
    const float* xrd = g_xr + (size_t)d * HC;
#pragma unroll
    for (int h = 0; h < HH; h++) {
        float sum = 0.f;
#pragma unroll
        for (int c0 = 0; c0 < CC; c0 += 32) {
            int c = c0 + lane;
            float z = xls[h * CC + c] + xrd[h * CC + c];
            z = z > 0.f ? z : 0.2f * z;
            sum += z * __ldg(&att[h * CC + c]);
        }
#pragma unroll
        for (int o = 16; o; o >>= 1) sum += __shfl_down_sync(0xffffffffu, sum, o);
        if (lane == 0) {
            g_e[w * HH + h] = sum;
            atomicMax(&g_emax[d * HH + h], fenc(sum));
        }
    }
}

__global__ void k_exp(const int* __restrict__ ei)
{
    int i = blockIdx.x * blockDim.x + threadIdx.x;
    if (i >= ETOT * HH) return;
    int e = i >> 3, h = i & 7;
    int d = (e < EE) ? ei[EE + e] : e - EE;
    float ex = expf(g_e[i] - fdec(g_emax[d * HH + h]));
    g_e[i] = ex;
    atomicAdd(&g_den[d * HH + h], ex);
}

__global__ void k_aggr(const int* __restrict__ ei)
{
    int e = blockIdx.x;
    int s, d;
    if (e < EE) { s = ei[e]; d = ei[EE + e]; } else { s = d = e - EE; }
    __shared__ float alpha[HH];
    if (threadIdx.x < HH)
        alpha[threadIdx.x] = g_e[e * HH + threadIdx.x] / g_den[d * HH + threadIdx.x];
    __syncthreads();
    const float* xls = g_xl + (size_t)s * HC;
    float* od = g_gat + (size_t)d * HC;
    for (int i = threadIdx.x; i < HC; i += blockDim.x)
        atomicAdd(&od[i], alpha[i >> 7] * xls[i]);
}

// ---------------- CNN over (1, 8, 128) per node ----------------
__global__ void k_conv(const float* __restrict__ gbias,
                       const float* __restrict__ cw1,  const float* __restrict__ cb1,
                       const float* __restrict__ cw4,  const float* __restrict__ cb4,
                       const float* __restrict__ cw16, const float* __restrict__ cb16,
                       const float* __restrict__ cw32, const float* __restrict__ cb32,
                       float* __restrict__ cnn)
{
    __shared__ float row[HC];
    __shared__ float w1[48], w4[192], w16[768], w32[1536];
    __shared__ float b[24];
    int n = blockIdx.x, tid = threadIdx.x;
    for (int i = tid; i < HC; i += blockDim.x)
        row[i] = g_gat[(size_t)n * HC + i] + gbias[i];
    for (int i = tid; i < 48;   i += blockDim.x) w1[i]  = cw1[i];
    for (int i = tid; i < 192;  i += blockDim.x) w4[i]  = cw4[i];
    for (int i = tid; i < 768;  i += blockDim.x) w16[i] = cw16[i];
    for (int i = tid; i < 1536; i += blockDim.x) w32[i] = cw32[i];
    if (tid < 6) { b[tid] = cb1[tid]; b[6+tid] = cb4[tid]; b[12+tid] = cb16[tid]; b[18+tid] = cb32[tid]; }
    __syncthreads();

    float* orow = cnn + (size_t)n * FDIM;
    for (int i = tid; i < FDIM; i += blockDim.x) {
        const float* w; int kw, o, x0, bb, j;
        if (i < 768)       { j = i;        kw = 1;  w = w1;  o = j / 128; x0 = j % 128; bb = 0;  }
        else if (i < 1518) { j = i - 768;  kw = 4;  w = w4;  o = j / 125; x0 = j % 125; bb = 6;  }
        else if (i < 2196) { j = i - 1518; kw = 16; w = w16; o = j / 113; x0 = j % 113; bb = 12; }
        else               { j = i - 2196; kw = 32; w = w32; o = j / 97;  x0 = j % 97;  bb = 18; }
        float s = b[bb + o];
        const float* wo = w + o * 8 * kw;
        for (int kh = 0; kh < 8; kh++)
            for (int x = 0; x < kw; x++)
                s += row[kh * 128 + x0 + x] * wo[kh * kw + x];
        orow[i] = s > 0.f ? s : 0.f;
    }
}

// ---------------- pair features (tf32-rounded, padded) ----------------
__global__ void k_feats(const int* __restrict__ pos, const int* __restrict__ neg,
                        const float* __restrict__ cnn)
{
    int p = blockIdx.x;
    int mi, di;
    if (p < PP) { mi = pos[p * 2]; di = pos[p * 2 + 1]; }
    else        { mi = neg[(p - PP) * 2]; di = neg[(p - PP) * 2 + 1]; }
    const float* a  = cnn + (size_t)mi * FDIM;
    const float* bb = cnn + (size_t)(NM + di) * FDIM;
    float* f = g_feats + (size_t)p * FPAD;
    for (int i = threadIdx.x; i < FPAD; i += blockDim.x) {
        float v = 0.f;
        if (i < FDIM) v = tf32_rna(a[i] * bb[i]);
        f[i] = v;
    }
}

// ---------------- final GEMV + sigmoid + labels ----------------
__global__ void k_final(const float* __restrict__ mw4, float* __restrict__ out,
                        int write_labels)
{
    int w = (blockIdx.x * blockDim.x + threadIdx.x) >> 5;
    int lane = threadIdx.x & 31;
    if (w >= NPAIR) return;
    const float* hrow = g_h3 + (size_t)w * D3P;
    float s = 0.f;
    for (int k = lane; k < D3; k += 32) s += hrow[k] * mw4[k];
#pragma unroll
    for (int o = 16; o; o >>= 1) s += __shfl_down_sync(0xffffffffu, s, o);
    if (lane == 0) {
        out[w] = 1.f / (1.f + expf(-s));
        if (write_labels) out[NPAIR + w] = (w < PP) ? 1.f : 0.f;
    }
}

// ---------------- launcher ----------------
static inline int cdiv(int a, int b) { return (a + b - 1) / b; }

extern "C" void kernel_launch(void* const* d_in, const int* in_sizes, int n_in,
                              void* d_out, int out_size)
{
    const float* mic   = (const float*)d_in[0];
    const float* dis   = (const float*)d_in[1];
    const int*   ei    = (const int*)  d_in[2];
    const int*   pos   = (const int*)  d_in[3];
    const int*   neg   = (const int*)  d_in[4];
    const float* W_mic = (const float*)d_in[6];
    const float* W_dis = (const float*)d_in[7];
    const float* Wl    = (const float*)d_in[8];
    const float* bl    = (const float*)d_in[9];
    const float* Wr    = (const float*)d_in[10];
    const float* br    = (const float*)d_in[11];
    const float* att   = (const float*)d_in[12];
    const float* gbias = (const float*)d_in[13];
    const float* cw1   = (const float*)d_in[14];
    const float* cb1   = (const float*)d_in[15];
    const float* cw4   = (const float*)d_in[16];
    const float* cb4   = (const float*)d_in[17];
    const float* cw16  = (const float*)d_in[18];
    const float* cb16  = (const float*)d_in[19];
    const float* cw32  = (const float*)d_in[20];
    const float* cb32  = (const float*)d_in[21];
    const float* mw1   = (const float*)d_in[22];
    const float* mb1   = (const float*)d_in[23];
    const float* mw2   = (const float*)d_in[24];
    const float* mb2   = (const float*)d_in[25];
    const float* mw3   = (const float*)d_in[26];
    const float* mb3   = (const float*)d_in[27];
    const float* mw4   = (const float*)d_in[28];
    float* out = (float*)d_out;

    float *p_h, *p_xl, *p_xr, *p_feats, *p_h1, *p_h2, *p_h3, *p_cnn;
    float *p_w1r, *p_w2r, *p_w3r;
    cudaGetSymbolAddress((void**)&p_h,     g_h);
    cudaGetSymbolAddress((void**)&p_xl,    g_xl);
    cudaGetSymbolAddress((void**)&p_xr,    g_xr);
    cudaGetSymbolAddress((void**)&p_feats, g_feats);
    cudaGetSymbolAddress((void**)&p_h1,    g_h1);
    cudaGetSymbolAddress((void**)&p_h2,    g_h2);
    cudaGetSymbolAddress((void**)&p_h3,    g_h3);
    cudaGetSymbolAddress((void**)&p_cnn,   g_cnn);
    cudaGetSymbolAddress((void**)&p_w1r,   g_w1r);
    cudaGetSymbolAddress((void**)&p_w2r,   g_w2r);
    cudaGetSymbolAddress((void**)&p_w3r,   g_w3r);

    // output layout: pred(80000) | labels(80000) | cnn_outputs(2300*2778)
    const int full = 2 * NPAIR + NN * FDIM;
    float* cnn = (out_size >= full) ? (out + 2 * NPAIR) : p_cnn;
    int write_labels = (out_size >= 2 * NPAIR) ? 1 : 0;

    cudaFuncSetAttribute(gemm_tc, cudaFuncAttributeMaxDynamicSharedMemorySize, SMEM_TC);

    dim3 blk(256);

    // weight pre-rounding (independent, launch first)
    k_round<<<cdiv(FPAD * D1, 256), 256>>>(mw1, p_w1r, FDIM, D1, FPAD * D1);
    k_round<<<cdiv(D1P * D2, 256), 256>>>(mw2, p_w2r, D1, D2, D1P * D2);
    k_round<<<cdiv(D2P * D3, 256), 256>>>(mw3, p_w3r, D2, D3, D2P * D3);

    // h = concat(mic @ W_mic, dis @ W_dis)
    sgemm<<<dim3(cdiv(CC, BN), cdiv(NM, BM)), blk>>>(mic, W_mic, nullptr, p_h,            NM, CC, NM, 0, 0.f);
    sgemm<<<dim3(cdiv(CC, BN), cdiv(ND, BM)), blk>>>(dis, W_dis, nullptr, p_h + NM * CC,  ND, CC, ND, 0, 0.f);

    // xl / xr
    sgemm<<<dim3(cdiv(HC, BN), cdiv(NN, BM)), blk>>>(p_h, Wl, bl, p_xl, NN, HC, CC, 0, 0.f);
    sgemm<<<dim3(cdiv(HC, BN), cdiv(NN, BM)), blk>>>(p_h, Wr, br, p_xr, NN, HC, CC, 0, 0.f);

    // GAT attention
    k_init<<<cdiv(NN * HC, 256), 256>>>();
    k_edge_e<<<cdiv(ETOT * 32, 256), 256>>>(ei, att);
    k_exp<<<cdiv(ETOT * HH, 256), 256>>>(ei);
    k_aggr<<<ETOT, 256>>>(ei);

    // CNN embeddings
    k_conv<<<NN, 256>>>(gbias, cw1, cb1, cw4, cb4, cw16, cb16, cw32, cb32, cnn);

    // pair features + tensor-core MLP
    k_feats<<<NPAIR, 256>>>(pos, neg, cnn);
    gemm_tc<<<dim3(D1P / 128, NPAIR / 128), blk, SMEM_TC>>>(p_feats, p_w1r, mb1, p_h1, D1, FPAD, D1P, 0.01f, 1);
    gemm_tc<<<dim3(cdiv(D2P, 128), NPAIR / 128), blk, SMEM_TC>>>(p_h1, p_w2r, mb2, p_h2, D2, D1P, D2P, 0.01f, 1);
    gemm_tc<<<dim3(cdiv(D3P, 128), NPAIR / 128), blk, SMEM_TC>>>(p_h2, p_w3r, mb3, p_h3, D3, D2P, D3P, 0.01f, 0);
    k_final<<<cdiv(NPAIR * 32, 256), 256>>>(mw4, out, write_labels);
}

// round 4
// speedup vs baseline: 3.5097x; 1.0235x over previous
#include <cuda_runtime.h>
#include <cstdint>

// ---------------- problem dimensions (fixed by the dataset) ----------------
#define NM    1500
#define ND    800
#define NN    2300          // NM + ND
#define CC    128
#define HH    8
#define HC    1024          // HH*CC
#define EE    80000
#define ETOT  (EE + NN)     // edges + self loops
#define PP    40000
#define NPAIR 80000
#define FDIM  2778
#define FPAD  2784          // mult of 32
#define D1    1389
#define D1P   1408          // mult of 128
#define D2    694
#define D2P   704           // output ld (mult of 32)
#define D2NT  768           // N padded to mult of 128
#define D3    463
#define D3P   464
#define D3NT  512

// ---------------- scratch ----------------
__device__ float    g_h    [NN * CC];
__device__ float    g_xl   [NN * HC];
__device__ float    g_xr   [NN * HC];
__device__ float    g_e    [ETOT * HH];
__device__ unsigned g_emax [NN * HH];
__device__ float    g_den  [NN * HH];
__device__ float    g_gat  [NN * HC];
__device__ float    g_cnn  [NN * FDIM];
__device__ float    g_feats[(size_t)NPAIR * FPAD];
__device__ float    g_h1   [(size_t)NPAIR * D1P];
__device__ float    g_h2   [(size_t)NPAIR * D2P];
__device__ float    g_h3   [(size_t)NPAIR * D3P];
__device__ float    g_w1t  [(size_t)D1P  * FPAD];   // W1^T [1408][2784]
__device__ float    g_w2t  [(size_t)D2NT * D1P];    // W2^T [768][1408]
__device__ float    g_w3t  [(size_t)D3NT * D2P];    // W3^T [512][704]

// ---------------- helpers ----------------
__device__ __forceinline__ unsigned fenc(float f) {
    unsigned u = __float_as_uint(f);
    return (u & 0x80000000u) ? ~u : (u | 0x80000000u);
}
__device__ __forceinline__ float fdec(unsigned u) {
    unsigned v = (u & 0x80000000u) ? (u ^ 0x80000000u) : ~u;
    return __uint_as_float(v);
}
__device__ __forceinline__ float tf32_rna(float v) {
    unsigned u;
    asm("cvt.rna.tf32.f32 %0, %1;" : "=r"(u) : "f"(v));
    return __uint_as_float(u);
}

// ---------------- tf32 mma.sync GEMM ----------------
// C[m, c] = act(sum_k A[m,k] * Bt[c,k] + bias[c]); A[M x Kp], Bt[Npad x Kp]
// (both tf32-pre-rounded). M mult of 128, Npad mult of 128, Kp mult of 32.
// Block 128x128x32, 8 warps (2x4), warp tile 64x32, 3-stage cp.async pipeline.
// Both smem tiles stride 36 -> conflict-free fragment loads.
#define ST 3
#define STG_F 9216                  // floats per stage: A 128*36 + B 128*36
#define SMEM_TC (ST * STG_F * 4)    // 110592 B

__global__ void __launch_bounds__(256)
gemm_tc(const float* __restrict__ A, const float* __restrict__ Bt,
        const float* __restrict__ bias, float* __restrict__ C,
        int Nreal, int Kp, int ldc, float slope, int round_out)
{
    extern __shared__ float sm[];
    const int tid  = threadIdx.x;
    const int lane = tid & 31, wid = tid >> 5;
    const int g = lane >> 2, tg = lane & 3;
    const int wm = wid & 1, wn = wid >> 1;          // 2 x 4 warp grid
    const int m0 = blockIdx.y * 128, n0 = blockIdx.x * 128;
    const unsigned smb = (unsigned)__cvta_generic_to_shared(sm);

    float acc[4][4][4];
#pragma unroll
    for (int a = 0; a < 4; a++)
#pragma unroll
        for (int b = 0; b < 4; b++)
#pragma unroll
            for (int c = 0; c < 4; c++) acc[a][b][c] = 0.f;

    auto fill = [&](int s, int kt) {
        unsigned ab = smb + (unsigned)(s * STG_F) * 4u;
        unsigned bb = ab + 4608u * 4u;
#pragma unroll
        for (int p = 0; p < 4; p++) {
            int i = p * 256 + tid;
            int row = i >> 3, c4 = (i & 7) * 4;
            unsigned off = (unsigned)(row * 36 + c4) * 4u;
            const float* srcA = A  + (size_t)(m0 + row) * Kp + kt + c4;
            const float* srcB = Bt + (size_t)(n0 + row) * Kp + kt + c4;
            asm volatile("cp.async.cg.shared.global [%0], [%1], 16;" :: "r"(ab + off), "l"(srcA));
            asm volatile("cp.async.cg.shared.global [%0], [%1], 16;" :: "r"(bb + off), "l"(srcB));
        }
        asm volatile("cp.async.commit_group;" ::: "memory");
    };

    const int T = Kp >> 5;
    fill(0, 0);
    if (T > 1) fill(1, 32);

    for (int t = 0; t < T; ++t) {
        if (t + 2 < T) {
            fill((t + 2) % ST, (t + 2) * 32);
            asm volatile("cp.async.wait_group 2;" ::: "memory");
        } else {
            asm volatile("cp.async.wait_group 0;" ::: "memory");
        }
        __syncthreads();

        const float* As = sm + (t % ST) * STG_F;
        const float* Bs = As + 4608;
#pragma unroll
        for (int kk = 0; kk < 4; ++kk) {
            const int k = kk * 8;
            unsigned a[4][4], b[4][2];
#pragma unroll
            for (int mt = 0; mt < 4; ++mt) {
                int rb = wm * 64 + mt * 16;
                a[mt][0] = __float_as_uint(As[(rb + g)     * 36 + k + tg]);
                a[mt][1] = __float_as_uint(As[(rb + 8 + g) * 36 + k + tg]);
                a[mt][2] = __float_as_uint(As[(rb + g)     * 36 + k + tg + 4]);
                a[mt][3] = __float_as_uint(As[(rb + 8 + g) * 36 + k + tg + 4]);
            }
#pragma unroll
            for (int nt = 0; nt < 4; ++nt) {
                int cb = wn * 32 + nt * 8;
                b[nt][0] = __float_as_uint(Bs[(cb + g) * 36 + k + tg]);
                b[nt][1] = __float_as_uint(Bs[(cb + g) * 36 + k + tg + 4]);
            }
#pragma unroll
            for (int mt = 0; mt < 4; ++mt)
#pragma unroll
                for (int nt = 0; nt < 4; ++nt)
                    asm volatile(
                        "mma.sync.aligned.m16n8k8.row.col.f32.tf32.tf32.f32 "
                        "{%0,%1,%2,%3}, {%4,%5,%6,%7}, {%8,%9}, {%0,%1,%2,%3};\n"
                        : "+f"(acc[mt][nt][0]), "+f"(acc[mt][nt][1]),
                          "+f"(acc[mt][nt][2]), "+f"(acc[mt][nt][3])
                        : "r"(a[mt][0]), "r"(a[mt][1]), "r"(a[mt][2]), "r"(a[mt][3]),
                          "r"(b[nt][0]), "r"(b[nt][1]));
        }
        __syncthreads();
    }

    // epilogue: bias + leaky-relu + optional tf32 rounding; zero pad cols [Nreal, ldc)
#pragma unroll
    for (int mt = 0; mt < 4; ++mt) {
#pragma unroll
        for (int nt = 0; nt < 4; ++nt) {
            int r0 = m0 + wm * 64 + mt * 16 + g;
            int c0 = n0 + wn * 32 + nt * 8 + 2 * tg;
#pragma unroll
            for (int e = 0; e < 4; ++e) {
                int r = r0 + (e >> 1) * 8;
                int c = c0 + (e & 1);
                if (c < ldc) {
                    float v = 0.f;
                    if (c < Nreal) {
                        v = acc[mt][nt][e] + __ldg(&bias[c]);
                        v = v > 0.f ? v : slope * v;
                        if (round_out) v = tf32_rna(v);
                    }
                    C[(size_t)r * ldc + c] = v;
                }
            }
        }
    }
}

// ---------------- weight transpose + tf32 round: dst[n][k] ----------------
__global__ void k_round_t(const float* __restrict__ src, float* __restrict__ dst,
                          int Ktrue, int Ntrue, int Kp, int total)
{
    int i = blockIdx.x * blockDim.x + threadIdx.x;
    if (i >= total) return;
    int n = i / Kp, k = i - n * Kp;
    float v = 0.f;
    if (n < Ntrue && k < Ktrue) v = tf32_rna(src[(size_t)k * Ntrue + n]);
    dst[i] = v;
}

__global__ void k_zero(float* p, int n)
{
    int i = blockIdx.x * blockDim.x + threadIdx.x;
    if (i < n) p[i] = 0.f;
}

// ---------------- fp32 tiled GEMM with optional split-K ----------------
#define BM 128
#define BN 128
#define BKK 8
#define TM 8
#define TN 8

__global__ void __launch_bounds__(256, 2)
sgemm(const float* __restrict__ A, const float* __restrict__ B,
      const float* __restrict__ bias, float* __restrict__ C,
      int M, int N, int K, int act, float slope)
{
    __shared__ float As[BKK][BM];
    __shared__ float Bs[BKK][BN];

    const int tid = threadIdx.x;
    const int m0 = blockIdx.y * BM;
    const int n0 = blockIdx.x * BN;

    int chunk = (K + gridDim.z - 1) / gridDim.z;
    int kb = blockIdx.z * chunk;
    int ke = min(K, kb + chunk);

    const int arow = tid >> 1;
    const int acol = (tid & 1) * 4;
    const int brow = tid >> 5;
    const int bcol = (tid & 31) * 4;
    const int tr = (tid >> 4) * TM;
    const int tc = (tid & 15) * TN;

    float acc[TM][TN];
#pragma unroll
    for (int i = 0; i < TM; i++)
#pragma unroll
        for (int j = 0; j < TN; j++) acc[i][j] = 0.f;

    for (int k0 = kb; k0 < ke; k0 += BKK) {
#pragma unroll
        for (int j = 0; j < 4; j++) {
            int k = k0 + acol + j;
            int mm = m0 + arow;
            As[acol + j][arow] = (mm < M && k < ke) ? A[(size_t)mm * K + k] : 0.f;
        }
#pragma unroll
        for (int j = 0; j < 4; j++) {
            int k = k0 + brow;
            int n = n0 + bcol + j;
            Bs[brow][bcol + j] = (k < ke && n < N) ? B[(size_t)k * N + n] : 0.f;
        }
        __syncthreads();
#pragma unroll
        for (int kk = 0; kk < BKK; kk++) {
            float ra[TM], rb[TN];
#pragma unroll
            for (int i = 0; i < TM; i++) ra[i] = As[kk][tr + i];
#pragma unroll
            for (int j = 0; j < TN; j++) rb[j] = Bs[kk][tc + j];
#pragma unroll
            for (int i = 0; i < TM; i++)
#pragma unroll
                for (int j = 0; j < TN; j++) acc[i][j] += ra[i] * rb[j];
        }
        __syncthreads();
    }

#pragma unroll
    for (int i = 0; i < TM; i++) {
        int mm = m0 + tr + i;
        if (mm >= M) continue;
#pragma unroll
        for (int j = 0; j < TN; j++) {
            int n = n0 + tc + j;
            if (n >= N) continue;
            float v = acc[i][j];
            if (act == 2) { atomicAdd(&C[(size_t)mm * N + n], v); continue; }
            if (bias) v += bias[n];
            if (act == 1) v = v > 0.f ? v : slope * v;
            C[(size_t)mm * N + n] = v;
        }
    }
}

// ---------------- GAT kernels ----------------
__global__ void k_init()
{
    int i = blockIdx.x * blockDim.x + threadIdx.x;
    if (i < NN * HC) g_gat[i] = 0.f;
    if (i < NN * HH) { g_emax[i] = 0u; g_den[i] = 0.f; }
}

__global__ void k_edge_e(const int* __restrict__ ei, const float* __restrict__ att)
{
    int w = (blockIdx.x * blockDim.x + threadIdx.x) >> 5;
    int lane = threadIdx.x & 31;
    if (w >= ETOT) return;
    int s, d;
    if (w < EE) { s = ei[w]; d = ei[EE + w]; } else { s = d = w - EE; }
    const float* xls = g_xl + (size_t)s * HC;
    const float* xrd = g_xr + (size_t)d * HC;
#pragma unroll
    for (int h = 0; h < HH; h++) {
        float sum = 0.f;
#pragma unroll
        for (int c0 = 0; c0 < CC; c0 += 32) {
            int c = c0 + lane;
            float z = xls[h * CC + c] + xrd[h * CC + c];
            z = z > 0.f ? z : 0.2f * z;
            sum += z * __ldg(&att[h * CC + c]);
        }
#pragma unroll
        for (int o = 16; o; o >>= 1) sum += __shfl_down_sync(0xffffffffu, sum, o);
        if (lane == 0) {
            g_e[w * HH + h] = sum;
            atomicMax(&g_emax[d * HH + h], fenc(sum));
        }
    }
}

__global__ void k_exp(const int* __restrict__ ei)
{
    int i = blockIdx.x * blockDim.x + threadIdx.x;
    if (i >= ETOT * HH) return;
    int e = i >> 3, h = i & 7;
    int d = (e < EE) ? ei[EE + e] : e - EE;
    float ex = expf(g_e[i] - fdec(g_emax[d * HH + h]));
    g_e[i] = ex;
    atomicAdd(&g_den[d * HH + h], ex);
}

__global__ void k_aggr(const int* __restrict__ ei)
{
    int e = blockIdx.x;
    int s, d;
    if (e < EE) { s = ei[e]; d = ei[EE + e]; } else { s = d = e - EE; }
    __shared__ float alpha[HH];
    if (threadIdx.x < HH)
        alpha[threadIdx.x] = g_e[e * HH + threadIdx.x] / g_den[d * HH + threadIdx.x];
    __syncthreads();
    const float* xls = g_xl + (size_t)s * HC;
    float* od = g_gat + (size_t)d * HC;
    for (int i = threadIdx.x; i < HC; i += blockDim.x)
        atomicAdd(&od[i], alpha[i >> 7] * xls[i]);
}

// ---------------- CNN ----------------
__global__ void k_conv(const float* __restrict__ gbias,
                       const float* __restrict__ cw1,  const float* __restrict__ cb1,
                       const float* __restrict__ cw4,  const float* __restrict__ cb4,
                       const float* __restrict__ cw16, const float* __restrict__ cb16,
                       const float* __restrict__ cw32, const float* __restrict__ cb32,
                       float* __restrict__ cnn)
{
    __shared__ float row[HC];
    __shared__ float w1[48], w4[192], w16[768], w32[1536];
    __shared__ float b[24];
    int n = blockIdx.x, tid = threadIdx.x;
    for (int i = tid; i < HC; i += blockDim.x)
        row[i] = g_gat[(size_t)n * HC + i] + gbias[i];
    for (int i = tid; i < 48;   i += blockDim.x) w1[i]  = cw1[i];
    for (int i = tid; i < 192;  i += blockDim.x) w4[i]  = cw4[i];
    for (int i = tid; i < 768;  i += blockDim.x) w16[i] = cw16[i];
    for (int i = tid; i < 1536; i += blockDim.x) w32[i] = cw32[i];
    if (tid < 6) { b[tid] = cb1[tid]; b[6+tid] = cb4[tid]; b[12+tid] = cb16[tid]; b[18+tid] = cb32[tid]; }
    __syncthreads();

    float* orow = cnn + (size_t)n * FDIM;
    for (int i = tid; i < FDIM; i += blockDim.x) {
        const float* w; int kw, o, x0, bb, j;
        if (i < 768)       { j = i;        kw = 1;  w = w1;  o = j / 128; x0 = j % 128; bb = 0;  }
        else if (i < 1518) { j = i - 768;  kw = 4;  w = w4;  o = j / 125; x0 = j % 125; bb = 6;  }
        else if (i < 2196) { j = i - 1518; kw = 16; w = w16; o = j / 113; x0 = j % 113; bb = 12; }
        else               { j = i - 2196; kw = 32; w = w32; o = j / 97;  x0 = j % 97;  bb = 18; }
        float s = b[bb + o];
        const float* wo = w + o * 8 * kw;
        for (int kh = 0; kh < 8; kh++)
            for (int x = 0; x < kw; x++)
                s += row[kh * 128 + x0 + x] * wo[kh * kw + x];
        orow[i] = s > 0.f ? s : 0.f;
    }
}

// ---------------- pair features ----------------
__global__ void k_feats(const int* __restrict__ pos, const int* __restrict__ neg,
                        const float* __restrict__ cnn)
{
    int p = blockIdx.x;
    int mi, di;
    if (p < PP) { mi = pos[p * 2]; di = pos[p * 2 + 1]; }
    else        { mi = neg[(p - PP) * 2]; di = neg[(p - PP) * 2 + 1]; }
    const float* a  = cnn + (size_t)mi * FDIM;
    const float* bb = cnn + (size_t)(NM + di) * FDIM;
    float* f = g_feats + (size_t)p * FPAD;
    for (int i = threadIdx.x; i < FPAD; i += blockDim.x) {
        float v = 0.f;
        if (i < FDIM) v = tf32_rna(a[i] * bb[i]);
        f[i] = v;
    }
}

// ---------------- final GEMV + sigmoid + labels ----------------
__global__ void k_final(const float* __restrict__ mw4, float* __restrict__ out,
                        int write_labels)
{
    int w = (blockIdx.x * blockDim.x + threadIdx.x) >> 5;
    int lane = threadIdx.x & 31;
    if (w >= NPAIR) return;
    const float* hrow = g_h3 + (size_t)w * D3P;
    float s = 0.f;
    for (int k = lane; k < D3; k += 32) s += hrow[k] * mw4[k];
#pragma unroll
    for (int o = 16; o; o >>= 1) s += __shfl_down_sync(0xffffffffu, s, o);
    if (lane == 0) {
        out[w] = 1.f / (1.f + expf(-s));
        if (write_labels) out[NPAIR + w] = (w < PP) ? 1.f : 0.f;
    }
}

// ---------------- launcher ----------------
static inline int cdiv(int a, int b) { return (a + b - 1) / b; }

extern "C" void kernel_launch(void* const* d_in, const int* in_sizes, int n_in,
                              void* d_out, int out_size)
{
    const float* mic   = (const float*)d_in[0];
    const float* dis   = (const float*)d_in[1];
    const int*   ei    = (const int*)  d_in[2];
    const int*   pos   = (const int*)  d_in[3];
    const int*   neg   = (const int*)  d_in[4];
    const float* W_mic = (const float*)d_in[6];
    const float* W_dis = (const float*)d_in[7];
    const float* Wl    = (const float*)d_in[8];
    const float* bl    = (const float*)d_in[9];
    const float* Wr    = (const float*)d_in[10];
    const float* br    = (const float*)d_in[11];
    const float* att   = (const float*)d_in[12];
    const float* gbias = (const float*)d_in[13];
    const float* cw1   = (const float*)d_in[14];
    const float* cb1   = (const float*)d_in[15];
    const float* cw4   = (const float*)d_in[16];
    const float* cb4   = (const float*)d_in[17];
    const float* cw16  = (const float*)d_in[18];
    const float* cb16  = (const float*)d_in[19];
    const float* cw32  = (const float*)d_in[20];
    const float* cb32  = (const float*)d_in[21];
    const float* mw1   = (const float*)d_in[22];
    const float* mb1   = (const float*)d_in[23];
    const float* mw2   = (const float*)d_in[24];
    const float* mb2   = (const float*)d_in[25];
    const float* mw3   = (const float*)d_in[26];
    const float* mb3   = (const float*)d_in[27];
    const float* mw4   = (const float*)d_in[28];
    float* out = (float*)d_out;

    float *p_h, *p_xl, *p_xr, *p_feats, *p_h1, *p_h2, *p_h3, *p_cnn;
    float *p_w1t, *p_w2t, *p_w3t;
    cudaGetSymbolAddress((void**)&p_h,     g_h);
    cudaGetSymbolAddress((void**)&p_xl,    g_xl);
    cudaGetSymbolAddress((void**)&p_xr,    g_xr);
    cudaGetSymbolAddress((void**)&p_feats, g_feats);
    cudaGetSymbolAddress((void**)&p_h1,    g_h1);
    cudaGetSymbolAddress((void**)&p_h2,    g_h2);
    cudaGetSymbolAddress((void**)&p_h3,    g_h3);
    cudaGetSymbolAddress((void**)&p_cnn,   g_cnn);
    cudaGetSymbolAddress((void**)&p_w1t,   g_w1t);
    cudaGetSymbolAddress((void**)&p_w2t,   g_w2t);
    cudaGetSymbolAddress((void**)&p_w3t,   g_w3t);

    const int full = 2 * NPAIR + NN * FDIM;
    float* cnn = (out_size >= full) ? (out + 2 * NPAIR) : p_cnn;
    int write_labels = (out_size >= 2 * NPAIR) ? 1 : 0;

    cudaFuncSetAttribute(gemm_tc, cudaFuncAttributeMaxDynamicSharedMemorySize, SMEM_TC);

    dim3 blk(256);

    // weight transposes (independent, launch first)
    k_round_t<<<cdiv(D1P * FPAD, 256), 256>>>(mw1, p_w1t, FDIM, D1, FPAD, D1P * FPAD);
    k_round_t<<<cdiv(D2NT * D1P, 256), 256>>>(mw2, p_w2t, D1, D2, D1P, D2NT * D1P);
    k_round_t<<<cdiv(D3NT * D2P, 256), 256>>>(mw3, p_w3t, D2, D3, D2P, D3NT * D2P);

    // h = concat(mic @ W_mic, dis @ W_dis)  (split-K + atomic add)
    k_zero<<<cdiv(NN * CC, 256), 256>>>(p_h, NN * CC);
    sgemm<<<dim3(1, cdiv(NM, BM), 8), blk>>>(mic, W_mic, nullptr, p_h,           NM, CC, NM, 2, 0.f);
    sgemm<<<dim3(1, cdiv(ND, BM), 4), blk>>>(dis, W_dis, nullptr, p_h + NM * CC, ND, CC, ND, 2, 0.f);

    // xl / xr
    sgemm<<<dim3(cdiv(HC, BN), cdiv(NN, BM), 1), blk>>>(p_h, Wl, bl, p_xl, NN, HC, CC, 0, 0.f);
    sgemm<<<dim3(cdiv(HC, BN), cdiv(NN, BM), 1), blk>>>(p_h, Wr, br, p_xr, NN, HC, CC, 0, 0.f);

    // GAT attention
    k_init<<<cdiv(NN * HC, 256), 256>>>();
    k_edge_e<<<cdiv(ETOT * 32, 256), 256>>>(ei, att);
    k_exp<<<cdiv(ETOT * HH, 256), 256>>>(ei);
    k_aggr<<<ETOT, 256>>>(ei);

    // CNN embeddings
    k_conv<<<NN, 256>>>(gbias, cw1, cb1, cw4, cb4, cw16, cb16, cw32, cb32, cnn);

    // pair features + tensor-core MLP
    k_feats<<<NPAIR, 256>>>(pos, neg, cnn);
    gemm_tc<<<dim3(D1P / 128, NPAIR / 128), blk, SMEM_TC>>>(p_feats, p_w1t, mb1, p_h1, D1, FPAD, D1P, 0.01f, 1);
    gemm_tc<<<dim3(D2NT / 128, NPAIR / 128), blk, SMEM_TC>>>(p_h1, p_w2t, mb2, p_h2, D2, D1P, D2P, 0.01f, 1);
    gemm_tc<<<dim3(D3NT / 128, NPAIR / 128), blk, SMEM_TC>>>(p_h2, p_w3t, mb3, p_h3, D3, D2P, D3P, 0.01f, 0);
    k_final<<<cdiv(NPAIR * 32, 256), 256>>>(mw4, out, write_labels);
}

// round 5
// speedup vs baseline: 6.3710x; 1.8153x over previous
#include <cuda_runtime.h>
#include <cuda_fp16.h>
#include <cstdint>

// ---------------- problem dimensions (fixed by the dataset) ----------------
#define NM    1500
#define ND    800
#define NN    2300          // NM + ND
#define CC    128
#define HH    8
#define HC    1024          // HH*CC
#define EE    80000
#define ETOT  (EE + NN)     // edges + self loops
#define PP    40000
#define NPAIR 80000
#define FDIM  2778
#define FPAD  2784          // mult of 32
#define D1    1389
#define D1P   1408          // mult of 128
#define D2    694
#define D2P   704           // output ld (mult of 32)
#define D2NT  768           // N padded to mult of 128
#define D3    463
#define D3P   464
#define D3NT  512

// ---------------- scratch ----------------
__device__ float    g_h    [NN * CC];
__device__ float    g_xl   [NN * HC];
__device__ float    g_xr   [NN * HC];
__device__ float    g_e    [ETOT * HH];
__device__ unsigned g_emax [NN * HH];
__device__ float    g_den  [NN * HH];
__device__ float    g_gat  [NN * HC];
__device__ float    g_cnn  [NN * FDIM];
__device__ __half   g_featsh[(size_t)NPAIR * FPAD];
__device__ __half   g_h1h  [(size_t)NPAIR * D1P];
__device__ __half   g_h2h  [(size_t)NPAIR * D2P];
__device__ __half   g_h3h  [(size_t)NPAIR * D3P];
__device__ __half   g_w1th [(size_t)D1P  * FPAD];   // W1^T [1408][2784]
__device__ __half   g_w2th [(size_t)D2NT * D1P];    // W2^T [768][1408]
__device__ __half   g_w3th [(size_t)D3NT * D2P];    // W3^T [512][704]

// ---------------- helpers ----------------
__device__ __forceinline__ unsigned fenc(float f) {
    unsigned u = __float_as_uint(f);
    return (u & 0x80000000u) ? ~u : (u | 0x80000000u);
}
__device__ __forceinline__ float fdec(unsigned u) {
    unsigned v = (u & 0x80000000u) ? (u ^ 0x80000000u) : ~u;
    return __uint_as_float(v);
}

// ---------------- fp16 mma.sync GEMM ----------------
// C[m, c] = act(sum_k A[m,k] * Bt[c,k] + bias[c]) ; A[M x Kp], Bt[Npad x Kp] in half.
// M mult of 128, Npad mult of 128, Kp mult of 32. C written as half [M x ldc].
// Block 128x128x32, 8 warps (2x4), warp tile 64x32, 4-stage cp.async,
// ldmatrix fragments, smem row stride 40 halves (80 B) -> conflict-free.
#define HST 4
#define HROW 40
#define HTILEB (128 * HROW * 2)          // 10240 B per operand tile
#define HSTGB  (2 * HTILEB)              // 20480 B per stage
#define SMEM_HC (HST * HSTGB)            // 81920 B

#define LDSM_X4(r0, r1, r2, r3, addr) \
    asm volatile("ldmatrix.sync.aligned.m8n8.x4.shared.b16 {%0,%1,%2,%3}, [%4];" \
        : "=r"(r0), "=r"(r1), "=r"(r2), "=r"(r3) : "r"(addr))

__global__ void __launch_bounds__(256)
gemm_hc(const __half* __restrict__ A, const __half* __restrict__ Bt,
        const float* __restrict__ bias, __half* __restrict__ C,
        int Nreal, int Kp, int ldc, float slope)
{
    extern __shared__ __half sm[];
    const int tid  = threadIdx.x;
    const int lane = tid & 31, wid = tid >> 5;
    const int g = lane >> 2, tg = lane & 3;
    const int wm = wid & 1, wn = wid >> 1;          // 2 x 4 warp grid
    const int m0 = blockIdx.y * 128, n0 = blockIdx.x * 128;
    const unsigned smb = (unsigned)__cvta_generic_to_shared(sm);

    float acc[4][4][4];
#pragma unroll
    for (int a = 0; a < 4; a++)
#pragma unroll
        for (int b = 0; b < 4; b++)
#pragma unroll
            for (int c = 0; c < 4; c++) acc[a][b][c] = 0.f;

    // per-lane ldmatrix address components (byte offsets inside a stage)
    //   A matrices: row = (lane&15), koff halves = (lane>>4)*8
    const unsigned a_off = (unsigned)(((lane & 15) * HROW + (lane >> 4) * 8) * 2);
    //   B x4 over an n-tile pair: n = ((lane>>4)<<3) + (lane&7), koff = ((lane>>3)&1)*8
    const unsigned b_off = (unsigned)(((((lane >> 4) << 3) + (lane & 7)) * HROW
                                      + ((lane >> 3) & 1) * 8) * 2);

    auto fill = [&](int s, int kt) {
        unsigned ab = smb + (unsigned)s * HSTGB;
        unsigned bb = ab + HTILEB;
#pragma unroll
        for (int p = 0; p < 2; p++) {
            int i = p * 256 + tid;
            int row = i >> 1, c8 = (i & 1) * 16;    // two 16B chunks per row pair? no:
            // 128 rows x 4 chunks(8 halves) = 512 chunks; 256 threads x 2
            row = i >> 2; int c = i & 3;
            unsigned off = (unsigned)((row * HROW + c * 8) * 2);
            const __half* srcA = A  + (size_t)(m0 + row) * Kp + kt + c * 8;
            const __half* srcB = Bt + (size_t)(n0 + row) * Kp + kt + c * 8;
            asm volatile("cp.async.cg.shared.global [%0], [%1], 16;" :: "r"(ab + off), "l"(srcA));
            asm volatile("cp.async.cg.shared.global [%0], [%1], 16;" :: "r"(bb + off), "l"(srcB));
        }
        asm volatile("cp.async.commit_group;" ::: "memory");
    };

    const int T = Kp >> 5;
    fill(0, 0);
    if (T > 1) fill(1, 32);
    if (T > 2) fill(2, 64);

    for (int t = 0; t < T; ++t) {
        if (t + 3 < T) {
            fill((t + 3) & 3, (t + 3) * 32);
            asm volatile("cp.async.wait_group 3;" ::: "memory");
        } else {
            asm volatile("cp.async.wait_group 0;" ::: "memory");
        }
        __syncthreads();

        unsigned ab = smb + (unsigned)(t & 3) * HSTGB;
        unsigned bb = ab + HTILEB;
#pragma unroll
        for (int kk = 0; kk < 2; ++kk) {            // two k16 steps per 32-tile
            const unsigned kb = (unsigned)(kk * 16 * 2);   // 16 halves = 32 B
            unsigned a[4][4], b[2][4];
#pragma unroll
            for (int mt = 0; mt < 4; ++mt) {
                unsigned ad = ab + (unsigned)((wm * 64 + mt * 16) * HROW * 2) + a_off + kb;
                LDSM_X4(a[mt][0], a[mt][1], a[mt][2], a[mt][3], ad);
            }
#pragma unroll
            for (int np = 0; np < 2; ++np) {        // n-tile pairs: nt = 2np, 2np+1
                unsigned bd = bb + (unsigned)((wn * 32 + np * 16) * HROW * 2) + b_off + kb;
                LDSM_X4(b[np][0], b[np][1], b[np][2], b[np][3], bd);
            }
#pragma unroll
            for (int mt = 0; mt < 4; ++mt)
#pragma unroll
                for (int nt = 0; nt < 4; ++nt) {
                    unsigned b0 = b[nt >> 1][(nt & 1) * 2];
                    unsigned b1 = b[nt >> 1][(nt & 1) * 2 + 1];
                    asm volatile(
                        "mma.sync.aligned.m16n8k16.row.col.f32.f16.f16.f32 "
                        "{%0,%1,%2,%3}, {%4,%5,%6,%7}, {%8,%9}, {%0,%1,%2,%3};\n"
                        : "+f"(acc[mt][nt][0]), "+f"(acc[mt][nt][1]),
                          "+f"(acc[mt][nt][2]), "+f"(acc[mt][nt][3])
                        : "r"(a[mt][0]), "r"(a[mt][1]), "r"(a[mt][2]), "r"(a[mt][3]),
                          "r"(b0), "r"(b1));
                }
        }
        __syncthreads();
    }

    // epilogue: bias + leaky-relu, write half2
#pragma unroll
    for (int mt = 0; mt < 4; ++mt) {
#pragma unroll
        for (int nt = 0; nt < 4; ++nt) {
            int r0 = m0 + wm * 64 + mt * 16 + g;
            int c0 = n0 + wn * 32 + nt * 8 + 2 * tg;
            if (c0 >= ldc) continue;
#pragma unroll
            for (int half_row = 0; half_row < 2; ++half_row) {
                int r = r0 + half_row * 8;
                float v0 = 0.f, v1 = 0.f;
                if (c0 < Nreal) {
                    v0 = acc[mt][nt][half_row * 2] + __ldg(&bias[c0]);
                    v0 = v0 > 0.f ? v0 : slope * v0;
                }
                if (c0 + 1 < Nreal) {
                    v1 = acc[mt][nt][half_row * 2 + 1] + __ldg(&bias[c0 + 1]);
                    v1 = v1 > 0.f ? v1 : slope * v1;
                }
                __half2 o = __floats2half2_rn(v0, v1);
                *reinterpret_cast<__half2*>(&C[(size_t)r * ldc + c0]) = o;
            }
        }
    }
}

// ---------------- weight transpose + fp16 convert: dst[n][k] ----------------
__global__ void k_round_th(const float* __restrict__ src, __half* __restrict__ dst,
                           int Ktrue, int Ntrue, int Kp, int total)
{
    int i = blockIdx.x * blockDim.x + threadIdx.x;
    if (i >= total) return;
    int n = i / Kp, k = i - n * Kp;
    float v = 0.f;
    if (n < Ntrue && k < Ktrue) v = src[(size_t)k * Ntrue + n];
    dst[i] = __float2half_rn(v);
}

__global__ void k_zero(float* p, int n)
{
    int i = blockIdx.x * blockDim.x + threadIdx.x;
    if (i < n) p[i] = 0.f;
}

// ---------------- fp32 tiled GEMM with optional split-K ----------------
#define BM 128
#define BN 128
#define BKK 8
#define TM 8
#define TN 8

__global__ void __launch_bounds__(256, 2)
sgemm(const float* __restrict__ A, const float* __restrict__ B,
      const float* __restrict__ bias, float* __restrict__ C,
      int M, int N, int K, int act, float slope)
{
    __shared__ float As[BKK][BM];
    __shared__ float Bs[BKK][BN];

    const int tid = threadIdx.x;
    const int m0 = blockIdx.y * BM;
    const int n0 = blockIdx.x * BN;

    int chunk = (K + gridDim.z - 1) / gridDim.z;
    int kb = blockIdx.z * chunk;
    int ke = min(K, kb + chunk);

    const int arow = tid >> 1;
    const int acol = (tid & 1) * 4;
    const int brow = tid >> 5;
    const int bcol = (tid & 31) * 4;
    const int tr = (tid >> 4) * TM;
    const int tc = (tid & 15) * TN;

    float acc[TM][TN];
#pragma unroll
    for (int i = 0; i < TM; i++)
#pragma unroll
        for (int j = 0; j < TN; j++) acc[i][j] = 0.f;

    for (int k0 = kb; k0 < ke; k0 += BKK) {
#pragma unroll
        for (int j = 0; j < 4; j++) {
            int k = k0 + acol + j;
            int mm = m0 + arow;
            As[acol + j][arow] = (mm < M && k < ke) ? A[(size_t)mm * K + k] : 0.f;
        }
#pragma unroll
        for (int j = 0; j < 4; j++) {
            int k = k0 + brow;
            int n = n0 + bcol + j;
            Bs[brow][bcol + j] = (k < ke && n < N) ? B[(size_t)k * N + n] : 0.f;
        }
        __syncthreads();
#pragma unroll
        for (int kk = 0; kk < BKK; kk++) {
            float ra[TM], rb[TN];
#pragma unroll
            for (int i = 0; i < TM; i++) ra[i] = As[kk][tr + i];
#pragma unroll
            for (int j = 0; j < TN; j++) rb[j] = Bs[kk][tc + j];
#pragma unroll
            for (int i = 0; i < TM; i++)
#pragma unroll
                for (int j = 0; j < TN; j++) acc[i][j] += ra[i] * rb[j];
        }
        __syncthreads();
    }

#pragma unroll
    for (int i = 0; i < TM; i++) {
        int mm = m0 + tr + i;
        if (mm >= M) continue;
#pragma unroll
        for (int j = 0; j < TN; j++) {
            int n = n0 + tc + j;
            if (n >= N) continue;
            float v = acc[i][j];
            if (act == 2) { atomicAdd(&C[(size_t)mm * N + n], v); continue; }
            if (bias) v += bias[n];
            if (act == 1) v = v > 0.f ? v : slope * v;
            C[(size_t)mm * N + n] = v;
        }
    }
}

// ---------------- GAT kernels ----------------
__global__ void k_init()
{
    int i = blockIdx.x * blockDim.x + threadIdx.x;
    if (i < NN * HC) g_gat[i] = 0.f;
    if (i < NN * HH) { g_emax[i] = 0u; g_den[i] = 0.f; }
}

__global__ void k_edge_e(const int* __restrict__ ei, const float* __restrict__ att)
{
    int w = (blockIdx.x * blockDim.x + threadIdx.x) >> 5;
    int lane = threadIdx.x & 31;
    if (w >= ETOT) return;
    int s, d;
    if (w < EE) { s = ei[w]; d = ei[EE + w]; } else { s = d = w - EE; }
    const float* xls = g_xl + (size_t)s * HC;
    const float* xrd = g_xr + (size_t)d * HC;
#pragma unroll
    for (int h = 0; h < HH; h++) {
        float sum = 0.f;
#pragma unroll
        for (int c0 = 0; c0 < CC; c0 += 32) {
            int c = c0 + lane;
            float z = xls[h * CC + c] + xrd[h * CC + c];
            z = z > 0.f ? z : 0.2f * z;
            sum += z * __ldg(&att[h * CC + c]);
        }
#pragma unroll
        for (int o = 16; o; o >>= 1) sum += __shfl_down_sync(0xffffffffu, sum, o);
        if (lane == 0) {
            g_e[w * HH + h] = sum;
            atomicMax(&g_emax[d * HH + h], fenc(sum));
        }
    }
}

__global__ void k_exp(const int* __restrict__ ei)
{
    int i = blockIdx.x * blockDim.x + threadIdx.x;
    if (i >= ETOT * HH) return;
    int e = i >> 3, h = i & 7;
    int d = (e < EE) ? ei[EE + e] : e - EE;
    float ex = expf(g_e[i] - fdec(g_emax[d * HH + h]));
    g_e[i] = ex;
    atomicAdd(&g_den[d * HH + h], ex);
}

__global__ void k_aggr(const int* __restrict__ ei)
{
    int e = blockIdx.x;
    int s, d;
    if (e < EE) { s = ei[e]; d = ei[EE + e]; } else { s = d = e - EE; }
    __shared__ float alpha[HH];
    if (threadIdx.x < HH)
        alpha[threadIdx.x] = g_e[e * HH + threadIdx.x] / g_den[d * HH + threadIdx.x];
    __syncthreads();
    const float* xls = g_xl + (size_t)s * HC;
    float* od = g_gat + (size_t)d * HC;
    for (int i = threadIdx.x; i < HC; i += blockDim.x)
        atomicAdd(&od[i], alpha[i >> 7] * xls[i]);
}

// ---------------- CNN ----------------
__global__ void k_conv(const float* __restrict__ gbias,
                       const float* __restrict__ cw1,  const float* __restrict__ cb1,
                       const float* __restrict__ cw4,  const float* __restrict__ cb4,
                       const float* __restrict__ cw16, const float* __restrict__ cb16,
                       const float* __restrict__ cw32, const float* __restrict__ cb32,
                       float* __restrict__ cnn)
{
    __shared__ float row[HC];
    __shared__ float w1[48], w4[192], w16[768], w32[1536];
    __shared__ float b[24];
    int n = blockIdx.x, tid = threadIdx.x;
    for (int i = tid; i < HC; i += blockDim.x)
        row[i] = g_gat[(size_t)n * HC + i] + gbias[i];
    for (int i = tid; i < 48;   i += blockDim.x) w1[i]  = cw1[i];
    for (int i = tid; i < 192;  i += blockDim.x) w4[i]  = cw4[i];
    for (int i = tid; i < 768;  i += blockDim.x) w16[i] = cw16[i];
    for (int i = tid; i < 1536; i += blockDim.x) w32[i] = cw32[i];
    if (tid < 6) { b[tid] = cb1[tid]; b[6+tid] = cb4[tid]; b[12+tid] = cb16[tid]; b[18+tid] = cb32[tid]; }
    __syncthreads();

    float* orow = cnn + (size_t)n * FDIM;
    for (int i = tid; i < FDIM; i += blockDim.x) {
        const float* w; int kw, o, x0, bb, j;
        if (i < 768)       { j = i;        kw = 1;  w = w1;  o = j / 128; x0 = j % 128; bb = 0;  }
        else if (i < 1518) { j = i - 768;  kw = 4;  w = w4;  o = j / 125; x0 = j % 125; bb = 6;  }
        else if (i < 2196) { j = i - 1518; kw = 16; w = w16; o = j / 113; x0 = j % 113; bb = 12; }
        else               { j = i - 2196; kw = 32; w = w32; o = j / 97;  x0 = j % 97;  bb = 18; }
        float s = b[bb + o];
        const float* wo = w + o * 8 * kw;
        for (int kh = 0; kh < 8; kh++)
            for (int x = 0; x < kw; x++)
                s += row[kh * 128 + x0 + x] * wo[kh * kw + x];
        orow[i] = s > 0.f ? s : 0.f;
    }
}

// ---------------- pair features (fp16, padded) ----------------
__global__ void k_feats(const int* __restrict__ pos, const int* __restrict__ neg,
                        const float* __restrict__ cnn)
{
    int p = blockIdx.x;
    int mi, di;
    if (p < PP) { mi = pos[p * 2]; di = pos[p * 2 + 1]; }
    else        { mi = neg[(p - PP) * 2]; di = neg[(p - PP) * 2 + 1]; }
    const float* a  = cnn + (size_t)mi * FDIM;
    const float* bb = cnn + (size_t)(NM + di) * FDIM;
    __half* f = g_featsh + (size_t)p * FPAD;
    for (int i = threadIdx.x; i < FPAD; i += blockDim.x) {
        float v = 0.f;
        if (i < FDIM) v = a[i] * bb[i];
        f[i] = __float2half_rn(v);
    }
}

// ---------------- final GEMV + sigmoid + labels ----------------
__global__ void k_final(const float* __restrict__ mw4, float* __restrict__ out,
                        int write_labels)
{
    int w = (blockIdx.x * blockDim.x + threadIdx.x) >> 5;
    int lane = threadIdx.x & 31;
    if (w >= NPAIR) return;
    const __half* hrow = g_h3h + (size_t)w * D3P;
    float s = 0.f;
    for (int k = lane; k < D3; k += 32) s += __half2float(hrow[k]) * mw4[k];
#pragma unroll
    for (int o = 16; o; o >>= 1) s += __shfl_down_sync(0xffffffffu, s, o);
    if (lane == 0) {
        out[w] = 1.f / (1.f + expf(-s));
        if (write_labels) out[NPAIR + w] = (w < PP) ? 1.f : 0.f;
    }
}

// ---------------- launcher ----------------
static inline int cdiv(int a, int b) { return (a + b - 1) / b; }

extern "C" void kernel_launch(void* const* d_in, const int* in_sizes, int n_in,
                              void* d_out, int out_size)
{
    const float* mic   = (const float*)d_in[0];
    const float* dis   = (const float*)d_in[1];
    const int*   ei    = (const int*)  d_in[2];
    const int*   pos   = (const int*)  d_in[3];
    const int*   neg   = (const int*)  d_in[4];
    const float* W_mic = (const float*)d_in[6];
    const float* W_dis = (const float*)d_in[7];
    const float* Wl    = (const float*)d_in[8];
    const float* bl    = (const float*)d_in[9];
    const float* Wr    = (const float*)d_in[10];
    const float* br    = (const float*)d_in[11];
    const float* att   = (const float*)d_in[12];
    const float* gbias = (const float*)d_in[13];
    const float* cw1   = (const float*)d_in[14];
    const float* cb1   = (const float*)d_in[15];
    const float* cw4   = (const float*)d_in[16];
    const float* cb4   = (const float*)d_in[17];
    const float* cw16  = (const float*)d_in[18];
    const float* cb16  = (const float*)d_in[19];
    const float* cw32  = (const float*)d_in[20];
    const float* cb32  = (const float*)d_in[21];
    const float* mw1   = (const float*)d_in[22];
    const float* mb1   = (const float*)d_in[23];
    const float* mw2   = (const float*)d_in[24];
    const float* mb2   = (const float*)d_in[25];
    const float* mw3   = (const float*)d_in[26];
    const float* mb3   = (const float*)d_in[27];
    const float* mw4   = (const float*)d_in[28];
    float* out = (float*)d_out;

    float *p_h, *p_xl, *p_xr, *p_cnn;
    __half *p_feats, *p_h1, *p_h2, *p_w1t, *p_w2t, *p_w3t;
    cudaGetSymbolAddress((void**)&p_h,     g_h);
    cudaGetSymbolAddress((void**)&p_xl,    g_xl);
    cudaGetSymbolAddress((void**)&p_xr,    g_xr);
    cudaGetSymbolAddress((void**)&p_cnn,   g_cnn);
    cudaGetSymbolAddress((void**)&p_feats, g_featsh);
    cudaGetSymbolAddress((void**)&p_h1,    g_h1h);
    cudaGetSymbolAddress((void**)&p_h2,    g_h2h);
    cudaGetSymbolAddress((void**)&p_w1t,   g_w1th);
    cudaGetSymbolAddress((void**)&p_w2t,   g_w2th);
    cudaGetSymbolAddress((void**)&p_w3t,   g_w3th);
    __half* p_h3; cudaGetSymbolAddress((void**)&p_h3, g_h3h);

    const int full = 2 * NPAIR + NN * FDIM;
    float* cnn = (out_size >= full) ? (out + 2 * NPAIR) : p_cnn;
    int write_labels = (out_size >= 2 * NPAIR) ? 1 : 0;

    cudaFuncSetAttribute(gemm_hc, cudaFuncAttributeMaxDynamicSharedMemorySize, SMEM_HC);

    dim3 blk(256);

    // weight transposes to fp16 (independent, launch first)
    k_round_th<<<cdiv(D1P * FPAD, 256), 256>>>(mw1, p_w1t, FDIM, D1, FPAD, D1P * FPAD);
    k_round_th<<<cdiv(D2NT * D1P, 256), 256>>>(mw2, p_w2t, D1, D2, D1P, D2NT * D1P);
    k_round_th<<<cdiv(D3NT * D2P, 256), 256>>>(mw3, p_w3t, D2, D3, D2P, D3NT * D2P);

    // h = concat(mic @ W_mic, dis @ W_dis)  (split-K + atomic add)
    k_zero<<<cdiv(NN * CC, 256), 256>>>(p_h, NN * CC);
    sgemm<<<dim3(1, cdiv(NM, BM), 8), blk>>>(mic, W_mic, nullptr, p_h,           NM, CC, NM, 2, 0.f);
    sgemm<<<dim3(1, cdiv(ND, BM), 4), blk>>>(dis, W_dis, nullptr, p_h + NM * CC, ND, CC, ND, 2, 0.f);

    // xl / xr
    sgemm<<<dim3(cdiv(HC, BN), cdiv(NN, BM), 1), blk>>>(p_h, Wl, bl, p_xl, NN, HC, CC, 0, 0.f);
    sgemm<<<dim3(cdiv(HC, BN), cdiv(NN, BM), 1), blk>>>(p_h, Wr, br, p_xr, NN, HC, CC, 0, 0.f);

    // GAT attention
    k_init<<<cdiv(NN * HC, 256), 256>>>();
    k_edge_e<<<cdiv(ETOT * 32, 256), 256>>>(ei, att);
    k_exp<<<cdiv(ETOT * HH, 256), 256>>>(ei);
    k_aggr<<<ETOT, 256>>>(ei);

    // CNN embeddings
    k_conv<<<NN, 256>>>(gbias, cw1, cb1, cw4, cb4, cw16, cb16, cw32, cb32, cnn);

    // pair features + fp16 tensor-core MLP
    k_feats<<<NPAIR, 256>>>(pos, neg, cnn);
    gemm_hc<<<dim3(D1P / 128, NPAIR / 128), blk, SMEM_HC>>>(p_feats, p_w1t, mb1, p_h1, D1, FPAD, D1P, 0.01f);
    gemm_hc<<<dim3(D2NT / 128, NPAIR / 128), blk, SMEM_HC>>>(p_h1, p_w2t, mb2, p_h2, D2, D1P, D2P, 0.01f);
    gemm_hc<<<dim3(D3NT / 128, NPAIR / 128), blk, SMEM_HC>>>(p_h2, p_w3t, mb3, p_h3, D3, D2P, D3P, 0.01f);
    k_final<<<cdiv(NPAIR * 32, 256), 256>>>(mw4, out, write_labels);
}

// round 6
// speedup vs baseline: 7.2442x; 1.1371x over previous
#include <cuda_runtime.h>
#include <cuda_fp16.h>
#include <cstdint>

// ---------------- problem dimensions (fixed by the dataset) ----------------
#define NM    1500
#define ND    800
#define NN    2300          // NM + ND
#define CC    128
#define HH    8
#define HC    1024          // HH*CC
#define EE    80000
#define ETOT  (EE + NN)     // edges + self loops
#define PP    40000
#define NPAIR 80000
#define FDIM  2778
#define FPAD  2784          // mult of 32
#define D1    1389
#define D1P   1408          // mult of 128
#define D2    694
#define D2P   704           // output ld (mult of 32)
#define D2NT  768           // N padded to mult of 128
#define D3    463
#define D3P   464
#define D3NT  512

// ---------------- scratch ----------------
__device__ float    g_h    [NN * CC];
__device__ float    g_xl   [NN * HC];
__device__ float    g_xr   [NN * HC];
__device__ float    g_e    [ETOT * HH];
__device__ float    g_gat  [NN * HC];
__device__ float    g_cnn  [NN * FDIM];
__device__ int      g_cnt  [NN];          // counts, then scatter cursors
__device__ int      g_off  [NN + 1];
__device__ int      g_sorted[ETOT];
__device__ __half   g_featsh[(size_t)NPAIR * FPAD];
__device__ __half   g_h1h  [(size_t)NPAIR * D1P];
__device__ __half   g_h2h  [(size_t)NPAIR * D2P];
__device__ __half   g_h3h  [(size_t)NPAIR * D3P];
__device__ __half   g_w1th [(size_t)D1P  * FPAD];
__device__ __half   g_w2th [(size_t)D2NT * D1P];
__device__ __half   g_w3th [(size_t)D3NT * D2P];

// ---------------- helpers ----------------
__device__ __forceinline__ unsigned fenc(float f) {
    unsigned u = __float_as_uint(f);
    return (u & 0x80000000u) ? ~u : (u | 0x80000000u);
}
__device__ __forceinline__ float fdec(unsigned u) {
    unsigned v = (u & 0x80000000u) ? (u ^ 0x80000000u) : ~u;
    return __uint_as_float(v);
}

// ---------------- fp16 mma.sync GEMM ----------------
// Block 128x128x32, 8 warps (2x4), warp tile 64x32, 3-stage cp.async, occ 2.
#define HST 3
#define HROW 40
#define HTILEB (128 * HROW * 2)          // 10240 B per operand tile
#define HSTGB  (2 * HTILEB)              // 20480 B per stage
#define SMEM_HC (HST * HSTGB)            // 61440 B

#define LDSM_X4(r0, r1, r2, r3, addr) \
    asm volatile("ldmatrix.sync.aligned.m8n8.x4.shared.b16 {%0,%1,%2,%3}, [%4];" \
        : "=r"(r0), "=r"(r1), "=r"(r2), "=r"(r3) : "r"(addr))

__global__ void __launch_bounds__(256, 2)
gemm_hc(const __half* __restrict__ A, const __half* __restrict__ Bt,
        const float* __restrict__ bias, __half* __restrict__ C,
        int Nreal, int Kp, int ldc, float slope)
{
    extern __shared__ __half sm[];
    const int tid  = threadIdx.x;
    const int lane = tid & 31, wid = tid >> 5;
    const int g = lane >> 2, tg = lane & 3;
    const int wm = wid & 1, wn = wid >> 1;
    const int m0 = blockIdx.y * 128, n0 = blockIdx.x * 128;
    const unsigned smb = (unsigned)__cvta_generic_to_shared(sm);

    float acc[4][4][4];
#pragma unroll
    for (int a = 0; a < 4; a++)
#pragma unroll
        for (int b = 0; b < 4; b++)
#pragma unroll
            for (int c = 0; c < 4; c++) acc[a][b][c] = 0.f;

    const unsigned a_off = (unsigned)(((lane & 15) * HROW + (lane >> 4) * 8) * 2);
    const unsigned b_off = (unsigned)(((((lane >> 4) << 3) + (lane & 7)) * HROW
                                      + ((lane >> 3) & 1) * 8) * 2);

    auto fill = [&](int s, int kt) {
        unsigned ab = smb + (unsigned)s * HSTGB;
        unsigned bb = ab + HTILEB;
#pragma unroll
        for (int p = 0; p < 2; p++) {
            int i = p * 256 + tid;
            int row = i >> 2, c = i & 3;
            unsigned off = (unsigned)((row * HROW + c * 8) * 2);
            const __half* srcA = A  + (size_t)(m0 + row) * Kp + kt + c * 8;
            const __half* srcB = Bt + (size_t)(n0 + row) * Kp + kt + c * 8;
            asm volatile("cp.async.cg.shared.global [%0], [%1], 16;" :: "r"(ab + off), "l"(srcA));
            asm volatile("cp.async.cg.shared.global [%0], [%1], 16;" :: "r"(bb + off), "l"(srcB));
        }
        asm volatile("cp.async.commit_group;" ::: "memory");
    };

    const int T = Kp >> 5;
    fill(0, 0);
    if (T > 1) fill(1, 32);

    for (int t = 0; t < T; ++t) {
        if (t + 2 < T) {
            fill((t + 2) % HST, (t + 2) * 32);
            asm volatile("cp.async.wait_group 2;" ::: "memory");
        } else {
            asm volatile("cp.async.wait_group 0;" ::: "memory");
        }
        __syncthreads();

        unsigned ab = smb + (unsigned)(t % HST) * HSTGB;
        unsigned bb = ab + HTILEB;
#pragma unroll
        for (int kk = 0; kk < 2; ++kk) {
            const unsigned kb = (unsigned)(kk * 16 * 2);
            unsigned a[4][4], b[2][4];
#pragma unroll
            for (int mt = 0; mt < 4; ++mt) {
                unsigned ad = ab + (unsigned)((wm * 64 + mt * 16) * HROW * 2) + a_off + kb;
                LDSM_X4(a[mt][0], a[mt][1], a[mt][2], a[mt][3], ad);
            }
#pragma unroll
            for (int np = 0; np < 2; ++np) {
                unsigned bd = bb + (unsigned)((wn * 32 + np * 16) * HROW * 2) + b_off + kb;
                LDSM_X4(b[np][0], b[np][1], b[np][2], b[np][3], bd);
            }
#pragma unroll
            for (int mt = 0; mt < 4; ++mt)
#pragma unroll
                for (int nt = 0; nt < 4; ++nt) {
                    unsigned b0 = b[nt >> 1][(nt & 1) * 2];
                    unsigned b1 = b[nt >> 1][(nt & 1) * 2 + 1];
                    asm volatile(
                        "mma.sync.aligned.m16n8k16.row.col.f32.f16.f16.f32 "
                        "{%0,%1,%2,%3}, {%4,%5,%6,%7}, {%8,%9}, {%0,%1,%2,%3};\n"
                        : "+f"(acc[mt][nt][0]), "+f"(acc[mt][nt][1]),
                          "+f"(acc[mt][nt][2]), "+f"(acc[mt][nt][3])
                        : "r"(a[mt][0]), "r"(a[mt][1]), "r"(a[mt][2]), "r"(a[mt][3]),
                          "r"(b0), "r"(b1));
                }
        }
        __syncthreads();
    }

#pragma unroll
    for (int mt = 0; mt < 4; ++mt) {
#pragma unroll
        for (int nt = 0; nt < 4; ++nt) {
            int r0 = m0 + wm * 64 + mt * 16 + g;
            int c0 = n0 + wn * 32 + nt * 8 + 2 * tg;
            if (c0 >= ldc) continue;
#pragma unroll
            for (int hr = 0; hr < 2; ++hr) {
                int r = r0 + hr * 8;
                float v0 = 0.f, v1 = 0.f;
                if (c0 < Nreal) {
                    v0 = acc[mt][nt][hr * 2] + __ldg(&bias[c0]);
                    v0 = v0 > 0.f ? v0 : slope * v0;
                }
                if (c0 + 1 < Nreal) {
                    v1 = acc[mt][nt][hr * 2 + 1] + __ldg(&bias[c0 + 1]);
                    v1 = v1 > 0.f ? v1 : slope * v1;
                }
                *reinterpret_cast<__half2*>(&C[(size_t)r * ldc + c0]) = __floats2half2_rn(v0, v1);
            }
        }
    }
}

// ---------------- weight transpose + fp16 convert ----------------
__global__ void k_round_th(const float* __restrict__ src, __half* __restrict__ dst,
                           int Ktrue, int Ntrue, int Kp, int total)
{
    int i = blockIdx.x * blockDim.x + threadIdx.x;
    if (i >= total) return;
    int n = i / Kp, k = i - n * Kp;
    float v = 0.f;
    if (n < Ntrue && k < Ktrue) v = src[(size_t)k * Ntrue + n];
    dst[i] = __float2half_rn(v);
}

__global__ void k_zero(float* p, int n)
{
    int i = blockIdx.x * blockDim.x + threadIdx.x;
    if (i < n) p[i] = 0.f;
}

// ---------------- fp32 tiled GEMM with optional split-K ----------------
#define BM 128
#define BN 128
#define BKK 8
#define TM 8
#define TN 8

__global__ void __launch_bounds__(256, 2)
sgemm(const float* __restrict__ A, const float* __restrict__ B,
      const float* __restrict__ bias, float* __restrict__ C,
      int M, int N, int K, int act, float slope)
{
    __shared__ float As[BKK][BM];
    __shared__ float Bs[BKK][BN];

    const int tid = threadIdx.x;
    const int m0 = blockIdx.y * BM;
    const int n0 = blockIdx.x * BN;

    int chunk = (K + gridDim.z - 1) / gridDim.z;
    int kb = blockIdx.z * chunk;
    int ke = min(K, kb + chunk);

    const int arow = tid >> 1;
    const int acol = (tid & 1) * 4;
    const int brow = tid >> 5;
    const int bcol = (tid & 31) * 4;
    const int tr = (tid >> 4) * TM;
    const int tc = (tid & 15) * TN;

    float acc[TM][TN];
#pragma unroll
    for (int i = 0; i < TM; i++)
#pragma unroll
        for (int j = 0; j < TN; j++) acc[i][j] = 0.f;

    for (int k0 = kb; k0 < ke; k0 += BKK) {
#pragma unroll
        for (int j = 0; j < 4; j++) {
            int k = k0 + acol + j;
            int mm = m0 + arow;
            As[acol + j][arow] = (mm < M && k < ke) ? A[(size_t)mm * K + k] : 0.f;
        }
#pragma unroll
        for (int j = 0; j < 4; j++) {
            int k = k0 + brow;
            int n = n0 + bcol + j;
            Bs[brow][bcol + j] = (k < ke && n < N) ? B[(size_t)k * N + n] : 0.f;
        }
        __syncthreads();
#pragma unroll
        for (int kk = 0; kk < BKK; kk++) {
            float ra[TM], rb[TN];
#pragma unroll
            for (int i = 0; i < TM; i++) ra[i] = As[kk][tr + i];
#pragma unroll
            for (int j = 0; j < TN; j++) rb[j] = Bs[kk][tc + j];
#pragma unroll
            for (int i = 0; i < TM; i++)
#pragma unroll
                for (int j = 0; j < TN; j++) acc[i][j] += ra[i] * rb[j];
        }
        __syncthreads();
    }

#pragma unroll
    for (int i = 0; i < TM; i++) {
        int mm = m0 + tr + i;
        if (mm >= M) continue;
#pragma unroll
        for (int j = 0; j < TN; j++) {
            int n = n0 + tc + j;
            if (n >= N) continue;
            float v = acc[i][j];
            if (act == 2) { atomicAdd(&C[(size_t)mm * N + n], v); continue; }
            if (bias) v += bias[n];
            if (act == 1) v = v > 0.f ? v : slope * v;
            C[(size_t)mm * N + n] = v;
        }
    }
}

// ---------------- GAT: edge logits ----------------
__global__ void k_edge_e(const int* __restrict__ ei, const float* __restrict__ att)
{
    int w = (blockIdx.x * blockDim.x + threadIdx.x) >> 5;
    int lane = threadIdx.x & 31;
    if (w >= ETOT) return;
    int s, d;
    if (w < EE) { s = ei[w]; d = ei[EE + w]; } else { s = d = w - EE; }
    const float* xls = g_xl + (size_t)s * HC;
    const float* xrd = g_xr + (size_t)d * HC;
#pragma unroll
    for (int h = 0; h < HH; h++) {
        float sum = 0.f;
#pragma unroll
        for (int c0 = 0; c0 < CC; c0 += 32) {
            int c = c0 + lane;
            float z = xls[h * CC + c] + xrd[h * CC + c];
            z = z > 0.f ? z : 0.2f * z;
            sum += z * __ldg(&att[h * CC + c]);
        }
#pragma unroll
        for (int o = 16; o; o >>= 1) sum += __shfl_down_sync(0xffffffffu, sum, o);
        if (lane == 0) g_e[w * HH + h] = sum;
    }
}

// ---------------- GAT: CSR build (counting sort by destination) ----------------
__global__ void k_cnt(const int* __restrict__ ei)
{
    int i = blockIdx.x * blockDim.x + threadIdx.x;
    if (i < NN) g_cnt[i] = 1;                       // self loop
    __threadfence_block();
    // separate grid-stride pass is unsafe in one kernel; counts done in k_cnt2
}
__global__ void k_cnt2(const int* __restrict__ ei)
{
    int i = blockIdx.x * blockDim.x + threadIdx.x;
    if (i < EE) atomicAdd(&g_cnt[ei[EE + i]], 1);
}
__global__ void k_scan()
{
    __shared__ int s[NN];
    int tid = threadIdx.x;
    for (int i = tid; i < NN; i += blockDim.x) s[i] = g_cnt[i];
    __syncthreads();
    if (tid == 0) {
        int run = 0;
        for (int i = 0; i < NN; i++) { int c = s[i]; s[i] = run; run += c; }
        g_off[NN] = run;
    }
    __syncthreads();
    for (int i = tid; i < NN; i += blockDim.x) { g_off[i] = s[i]; g_cnt[i] = s[i]; }
}
__global__ void k_scatter(const int* __restrict__ ei)
{
    int i = blockIdx.x * blockDim.x + threadIdx.x;
    if (i >= ETOT) return;
    int dst = (i < EE) ? ei[EE + i] : i - EE;
    int pos = atomicAdd(&g_cnt[dst], 1);
    g_sorted[pos] = i;
}

// ---------------- GAT: per-destination softmax + aggregate (no gmem atomics) ----------------
#define ACH 128
__global__ void __launch_bounds__(256)
k_aggr2(const int* __restrict__ ei)
{
    const int d = blockIdx.x;
    const int tid = threadIdx.x;
    const int wid = tid >> 5, lane = tid & 31;
    const int beg = g_off[d], end = g_off[d + 1];
    const int nE = end - beg;

    __shared__ float ex_s[ACH][HH];
    __shared__ int   src_s[ACH];
    __shared__ unsigned mxu[HH];

    if (tid < HH) mxu[tid] = 0u;
    __syncthreads();

    // pass 1: per-head max
    for (int j = tid; j < nE * HH; j += 256) {
        int e = g_sorted[beg + (j >> 3)];
        atomicMax(&mxu[j & 7], fenc(g_e[e * HH + (j & 7)]));
    }
    __syncthreads();

    const int h = wid;                       // warp handles one head
    const float mxh = fdec(mxu[h]);
    const int cbase = h * CC + lane * 4;

    float a0 = 0.f, a1 = 0.f, a2 = 0.f, a3 = 0.f, denp = 0.f;

    for (int c0 = 0; c0 < nE; c0 += ACH) {
        int n = min(ACH, nE - c0);
        __syncthreads();
        for (int j = tid; j < n * HH; j += 256) {
            int ii = j >> 3, hh = j & 7;
            int e = g_sorted[beg + c0 + ii];
            ex_s[ii][hh] = __expf(g_e[e * HH + hh] - fdec(mxu[hh]));
        }
        for (int j = tid; j < n; j += 256) {
            int e = g_sorted[beg + c0 + j];
            src_s[j] = (e < EE) ? ei[e] : e - EE;
        }
        __syncthreads();
        for (int i = 0; i < n; i++) {
            float exv = ex_s[i][h];
            const float4 x = *reinterpret_cast<const float4*>(
                &g_xl[(size_t)src_s[i] * HC + cbase]);
            a0 += exv * x.x; a1 += exv * x.y; a2 += exv * x.z; a3 += exv * x.w;
        }
        for (int i = lane; i < n; i += 32) denp += ex_s[i][h];
    }
#pragma unroll
    for (int o = 16; o; o >>= 1) denp += __shfl_xor_sync(0xffffffffu, denp, o);
    float inv = 1.f / denp;
    float4 o4 = make_float4(a0 * inv, a1 * inv, a2 * inv, a3 * inv);
    *reinterpret_cast<float4*>(&g_gat[(size_t)d * HC + cbase]) = o4;
}

// ---------------- CNN ----------------
__global__ void k_conv(const float* __restrict__ gbias,
                       const float* __restrict__ cw1,  const float* __restrict__ cb1,
                       const float* __restrict__ cw4,  const float* __restrict__ cb4,
                       const float* __restrict__ cw16, const float* __restrict__ cb16,
                       const float* __restrict__ cw32, const float* __restrict__ cb32,
                       float* __restrict__ cnn)
{
    __shared__ float row[HC];
    __shared__ float w1[48], w4[192], w16[768], w32[1536];
    __shared__ float b[24];
    int n = blockIdx.x, tid = threadIdx.x;
    for (int i = tid; i < HC; i += blockDim.x)
        row[i] = g_gat[(size_t)n * HC + i] + gbias[i];
    for (int i = tid; i < 48;   i += blockDim.x) w1[i]  = cw1[i];
    for (int i = tid; i < 192;  i += blockDim.x) w4[i]  = cw4[i];
    for (int i = tid; i < 768;  i += blockDim.x) w16[i] = cw16[i];
    for (int i = tid; i < 1536; i += blockDim.x) w32[i] = cw32[i];
    if (tid < 6) { b[tid] = cb1[tid]; b[6+tid] = cb4[tid]; b[12+tid] = cb16[tid]; b[18+tid] = cb32[tid]; }
    __syncthreads();

    float* orow = cnn + (size_t)n * FDIM;
    for (int i = tid; i < FDIM; i += blockDim.x) {
        const float* w; int kw, o, x0, bb, j;
        if (i < 768)       { j = i;        kw = 1;  w = w1;  o = j / 128; x0 = j % 128; bb = 0;  }
        else if (i < 1518) { j = i - 768;  kw = 4;  w = w4;  o = j / 125; x0 = j % 125; bb = 6;  }
        else if (i < 2196) { j = i - 1518; kw = 16; w = w16; o = j / 113; x0 = j % 113; bb = 12; }
        else               { j = i - 2196; kw = 32; w = w32; o = j / 97;  x0 = j % 97;  bb = 18; }
        float s = b[bb + o];
        const float* wo = w + o * 8 * kw;
        for (int kh = 0; kh < 8; kh++)
            for (int x = 0; x < kw; x++)
                s += row[kh * 128 + x0 + x] * wo[kh * kw + x];
        orow[i] = s > 0.f ? s : 0.f;
    }
}

// ---------------- pair features (fp16, padded, half2 stores) ----------------
__global__ void k_feats(const int* __restrict__ pos, const int* __restrict__ neg,
                        const float* __restrict__ cnn)
{
    int p = blockIdx.x;
    int mi, di;
    if (p < PP) { mi = pos[p * 2]; di = pos[p * 2 + 1]; }
    else        { mi = neg[(p - PP) * 2]; di = neg[(p - PP) * 2 + 1]; }
    const float* a  = cnn + (size_t)mi * FDIM;
    const float* bb = cnn + (size_t)(NM + di) * FDIM;
    __half2* f = reinterpret_cast<__half2*>(g_featsh + (size_t)p * FPAD);
    for (int i = threadIdx.x; i < FPAD / 2; i += blockDim.x) {
        int c = i * 2;
        float v0 = (c     < FDIM) ? a[c]     * bb[c]     : 0.f;
        float v1 = (c + 1 < FDIM) ? a[c + 1] * bb[c + 1] : 0.f;
        f[i] = __floats2half2_rn(v0, v1);
    }
}

// ---------------- final GEMV + sigmoid + labels ----------------
__global__ void k_final(const float* __restrict__ mw4, float* __restrict__ out,
                        int write_labels)
{
    int w = (blockIdx.x * blockDim.x + threadIdx.x) >> 5;
    int lane = threadIdx.x & 31;
    if (w >= NPAIR) return;
    const __half* hrow = g_h3h + (size_t)w * D3P;
    float s = 0.f;
    for (int k = lane; k < D3; k += 32) s += __half2float(hrow[k]) * mw4[k];
#pragma unroll
    for (int o = 16; o; o >>= 1) s += __shfl_down_sync(0xffffffffu, s, o);
    if (lane == 0) {
        out[w] = 1.f / (1.f + expf(-s));
        if (write_labels) out[NPAIR + w] = (w < PP) ? 1.f : 0.f;
    }
}

// ---------------- launcher ----------------
static inline int cdiv(int a, int b) { return (a + b - 1) / b; }

extern "C" void kernel_launch(void* const* d_in, const int* in_sizes, int n_in,
                              void* d_out, int out_size)
{
    const float* mic   = (const float*)d_in[0];
    const float* dis   = (const float*)d_in[1];
    const int*   ei    = (const int*)  d_in[2];
    const int*   pos   = (const int*)  d_in[3];
    const int*   neg   = (const int*)  d_in[4];
    const float* W_mic = (const float*)d_in[6];
    const float* W_dis = (const float*)d_in[7];
    const float* Wl    = (const float*)d_in[8];
    const float* bl    = (const float*)d_in[9];
    const float* Wr    = (const float*)d_in[10];
    const float* br    = (const float*)d_in[11];
    const float* att   = (const float*)d_in[12];
    const float* gbias = (const float*)d_in[13];
    const float* cw1   = (const float*)d_in[14];
    const float* cb1   = (const float*)d_in[15];
    const float* cw4   = (const float*)d_in[16];
    const float* cb4   = (const float*)d_in[17];
    const float* cw16  = (const float*)d_in[18];
    const float* cb16  = (const float*)d_in[19];
    const float* cw32  = (const float*)d_in[20];
    const float* cb32  = (const float*)d_in[21];
    const float* mw1   = (const float*)d_in[22];
    const float* mb1   = (const float*)d_in[23];
    const float* mw2   = (const float*)d_in[24];
    const float* mb2   = (const float*)d_in[25];
    const float* mw3   = (const float*)d_in[26];
    const float* mb3   = (const float*)d_in[27];
    const float* mw4   = (const float*)d_in[28];
    float* out = (float*)d_out;

    float *p_h, *p_xl, *p_xr, *p_cnn;
    __half *p_feats, *p_h1, *p_h2, *p_h3, *p_w1t, *p_w2t, *p_w3t;
    cudaGetSymbolAddress((void**)&p_h,     g_h);
    cudaGetSymbolAddress((void**)&p_xl,    g_xl);
    cudaGetSymbolAddress((void**)&p_xr,    g_xr);
    cudaGetSymbolAddress((void**)&p_cnn,   g_cnn);
    cudaGetSymbolAddress((void**)&p_feats, g_featsh);
    cudaGetSymbolAddress((void**)&p_h1,    g_h1h);
    cudaGetSymbolAddress((void**)&p_h2,    g_h2h);
    cudaGetSymbolAddress((void**)&p_h3,    g_h3h);
    cudaGetSymbolAddress((void**)&p_w1t,   g_w1th);
    cudaGetSymbolAddress((void**)&p_w2t,   g_w2th);
    cudaGetSymbolAddress((void**)&p_w3t,   g_w3th);

    const int full = 2 * NPAIR + NN * FDIM;
    float* cnn = (out_size >= full) ? (out + 2 * NPAIR) : p_cnn;
    int write_labels = (out_size >= 2 * NPAIR) ? 1 : 0;

    cudaFuncSetAttribute(gemm_hc, cudaFuncAttributeMaxDynamicSharedMemorySize, SMEM_HC);

    dim3 blk(256);

    // weight transposes to fp16 (independent, launch first)
    k_round_th<<<cdiv(D1P * FPAD, 256), 256>>>(mw1, p_w1t, FDIM, D1, FPAD, D1P * FPAD);
    k_round_th<<<cdiv(D2NT * D1P, 256), 256>>>(mw2, p_w2t, D1, D2, D1P, D2NT * D1P);
    k_round_th<<<cdiv(D3NT * D2P, 256), 256>>>(mw3, p_w3t, D2, D3, D2P, D3NT * D2P);

    // CSR build (independent of features)
    k_cnt<<<cdiv(NN, 256), 256>>>(ei);
    k_cnt2<<<cdiv(EE, 256), 256>>>(ei);
    k_scan<<<1, 256>>>();
    k_scatter<<<cdiv(ETOT, 256), 256>>>(ei);

    // h = concat(mic @ W_mic, dis @ W_dis)  (split-K + atomic add)
    k_zero<<<cdiv(NN * CC, 256), 256>>>(p_h, NN * CC);
    sgemm<<<dim3(1, cdiv(NM, BM), 8), blk>>>(mic, W_mic, nullptr, p_h,           NM, CC, NM, 2, 0.f);
    sgemm<<<dim3(1, cdiv(ND, BM), 4), blk>>>(dis, W_dis, nullptr, p_h + NM * CC, ND, CC, ND, 2, 0.f);

    // xl / xr
    sgemm<<<dim3(cdiv(HC, BN), cdiv(NN, BM), 1), blk>>>(p_h, Wl, bl, p_xl, NN, HC, CC, 0, 0.f);
    sgemm<<<dim3(cdiv(HC, BN), cdiv(NN, BM), 1), blk>>>(p_h, Wr, br, p_xr, NN, HC, CC, 0, 0.f);

    // GAT attention
    k_edge_e<<<cdiv(ETOT * 32, 256), 256>>>(ei, att);
    k_aggr2<<<NN, 256>>>(ei);

    // CNN embeddings
    k_conv<<<NN, 256>>>(gbias, cw1, cb1, cw4, cb4, cw16, cb16, cw32, cb32, cnn);

    // pair features + fp16 tensor-core MLP
    k_feats<<<NPAIR, 256>>>(pos, neg, cnn);
    gemm_hc<<<dim3(D1P / 128, NPAIR / 128), blk, SMEM_HC>>>(p_feats, p_w1t, mb1, p_h1, D1, FPAD, D1P, 0.01f);
    gemm_hc<<<dim3(D2NT / 128, NPAIR / 128), blk, SMEM_HC>>>(p_h1, p_w2t, mb2, p_h2, D2, D1P, D2P, 0.01f);
    gemm_hc<<<dim3(D3NT / 128, NPAIR / 128), blk, SMEM_HC>>>(p_h2, p_w3t, mb3, p_h3, D3, D2P, D3P, 0.01f);
    k_final<<<cdiv(NPAIR * 32, 256), 256>>>(mw4, out, write_labels);
}

// round 7
// speedup vs baseline: 8.1684x; 1.1276x over previous
#include <cuda_runtime.h>
#include <cuda_fp16.h>
#include <cstdint>

// ---------------- problem dimensions ----------------
#define NM    1500
#define ND    800
#define NN    2300
#define NNP   2304          // NN padded to mult of 128
#define CC    128
#define HH    8
#define HC    1024
#define EE    80000
#define ETOT  (EE + NN)
#define PP    40000
#define NPAIR 80000
#define FDIM  2778
#define FPAD  2816          // mult of 64
#define D1    1389
#define D1P   1408
#define D2    694
#define D2P   704
#define D2NT  768
#define D3    463
#define D3P   464
#define D3NT  512

// ---------------- scratch ----------------
__device__ float    g_h    [NNP * CC];
__device__ __half   g_hh   [NNP * CC];
__device__ float    g_xl   [NNP * HC];
__device__ float    g_xr   [NNP * HC];
__device__ float    g_e    [ETOT * HH];
__device__ float    g_gat  [NN * HC];
__device__ float    g_cnn  [NN * FDIM];
__device__ int      g_cnt  [NN];
__device__ int      g_off  [NN + 1];
__device__ int      g_sorted[ETOT];
__device__ __half   g_featsh[(size_t)NPAIR * FPAD];
__device__ __half   g_h1h  [(size_t)NPAIR * D1P];
__device__ __half   g_h2h  [(size_t)NPAIR * D2P];
__device__ __half   g_h3h  [(size_t)NPAIR * D3P];
__device__ __half   g_w1th [(size_t)D1P  * FPAD];
__device__ __half   g_w2th [(size_t)D2NT * D1P];
__device__ __half   g_w3th [(size_t)D3NT * D2P];
__device__ __half   g_wlth [HC * CC];
__device__ __half   g_wrth [HC * CC];

// ---------------- helpers ----------------
__device__ __forceinline__ unsigned fenc(float f) {
    unsigned u = __float_as_uint(f);
    return (u & 0x80000000u) ? ~u : (u | 0x80000000u);
}
__device__ __forceinline__ float fdec(unsigned u) {
    unsigned v = (u & 0x80000000u) ? (u ^ 0x80000000u) : ~u;
    return __uint_as_float(v);
}

// ---------------- fp16 mma.sync GEMM, BK=64, 2-stage, occ 2 ----------------
// C[m,c] = act(sum_k A[m,k]*Bt[c,k] + bias[c]); A[M x Kp], Bt[Npad x Kp] half.
// M mult 128, Npad mult 128, Kp mult 64. out: fp16 (ld ldc) or fp32 (flag).
#define HROWB 72
#define HTILE2 (128 * HROWB * 2)      // 18432 B
#define HSTG2  (2 * HTILE2)           // 36864 B
#define SMEM_HC (2 * HSTG2)           // 73728 B

#define LDSM_X4(r0, r1, r2, r3, addr) \
    asm volatile("ldmatrix.sync.aligned.m8n8.x4.shared.b16 {%0,%1,%2,%3}, [%4];" \
        : "=r"(r0), "=r"(r1), "=r"(r2), "=r"(r3) : "r"(addr))

__global__ void __launch_bounds__(256, 2)
gemm_hc(const __half* __restrict__ A, const __half* __restrict__ Bt,
        const float* __restrict__ bias, void* __restrict__ Cv,
        int Nreal, int Kp, int ldc, float slope, int fp32_out)
{
    extern __shared__ __half sm[];
    const int tid  = threadIdx.x;
    const int lane = tid & 31, wid = tid >> 5;
    const int g = lane >> 2, tg = lane & 3;
    const int wm = wid & 1, wn = wid >> 1;
    const int m0 = blockIdx.y * 128, n0 = blockIdx.x * 128;
    const unsigned smb = (unsigned)__cvta_generic_to_shared(sm);

    float acc[4][4][4];
#pragma unroll
    for (int a = 0; a < 4; a++)
#pragma unroll
        for (int b = 0; b < 4; b++)
#pragma unroll
            for (int c = 0; c < 4; c++) acc[a][b][c] = 0.f;

    const unsigned a_off = (unsigned)(((lane & 15) * HROWB + (lane >> 4) * 8) * 2);
    const unsigned b_off = (unsigned)(((((lane >> 4) << 3) + (lane & 7)) * HROWB
                                      + ((lane >> 3) & 1) * 8) * 2);

    auto fill = [&](int s, int kt) {
        unsigned ab = smb + (unsigned)s * HSTG2;
        unsigned bb = ab + HTILE2;
#pragma unroll
        for (int p = 0; p < 4; p++) {
            int i = p * 256 + tid;
            int row = i >> 3, c = i & 7;
            unsigned off = (unsigned)((row * HROWB + c * 8) * 2);
            const __half* srcA = A  + (size_t)(m0 + row) * Kp + kt + c * 8;
            const __half* srcB = Bt + (size_t)(n0 + row) * Kp + kt + c * 8;
            asm volatile("cp.async.cg.shared.global [%0], [%1], 16;" :: "r"(ab + off), "l"(srcA));
            asm volatile("cp.async.cg.shared.global [%0], [%1], 16;" :: "r"(bb + off), "l"(srcB));
        }
        asm volatile("cp.async.commit_group;" ::: "memory");
    };

    const int T = Kp >> 6;
    fill(0, 0);
    if (T > 1) fill(1, 64);

    for (int t = 0; t < T; ++t) {
        if (t < T - 1) asm volatile("cp.async.wait_group 1;" ::: "memory");
        else           asm volatile("cp.async.wait_group 0;" ::: "memory");
        __syncthreads();

        unsigned ab = smb + (unsigned)(t & 1) * HSTG2;
        unsigned bb = ab + HTILE2;
#pragma unroll
        for (int kk = 0; kk < 4; ++kk) {
            const unsigned kb = (unsigned)(kk * 32);     // 16 halves = 32 B
            unsigned a[4][4], b[2][4];
#pragma unroll
            for (int mt = 0; mt < 4; ++mt) {
                unsigned ad = ab + (unsigned)((wm * 64 + mt * 16) * HROWB * 2) + a_off + kb;
                LDSM_X4(a[mt][0], a[mt][1], a[mt][2], a[mt][3], ad);
            }
#pragma unroll
            for (int np = 0; np < 2; ++np) {
                unsigned bd = bb + (unsigned)((wn * 32 + np * 16) * HROWB * 2) + b_off + kb;
                LDSM_X4(b[np][0], b[np][1], b[np][2], b[np][3], bd);
            }
#pragma unroll
            for (int mt = 0; mt < 4; ++mt)
#pragma unroll
                for (int nt = 0; nt < 4; ++nt) {
                    unsigned b0 = b[nt >> 1][(nt & 1) * 2];
                    unsigned b1 = b[nt >> 1][(nt & 1) * 2 + 1];
                    asm volatile(
                        "mma.sync.aligned.m16n8k16.row.col.f32.f16.f16.f32 "
                        "{%0,%1,%2,%3}, {%4,%5,%6,%7}, {%8,%9}, {%0,%1,%2,%3};\n"
                        : "+f"(acc[mt][nt][0]), "+f"(acc[mt][nt][1]),
                          "+f"(acc[mt][nt][2]), "+f"(acc[mt][nt][3])
                        : "r"(a[mt][0]), "r"(a[mt][1]), "r"(a[mt][2]), "r"(a[mt][3]),
                          "r"(b0), "r"(b1));
                }
        }
        __syncthreads();
        if (t + 2 < T) fill(t & 1, (t + 2) * 64);
    }

#pragma unroll
    for (int mt = 0; mt < 4; ++mt) {
#pragma unroll
        for (int nt = 0; nt < 4; ++nt) {
            int r0 = m0 + wm * 64 + mt * 16 + g;
            int c0 = n0 + wn * 32 + nt * 8 + 2 * tg;
            if (c0 >= ldc) continue;
#pragma unroll
            for (int hr = 0; hr < 2; ++hr) {
                int r = r0 + hr * 8;
                float v0 = 0.f, v1 = 0.f;
                if (c0 < Nreal) {
                    v0 = acc[mt][nt][hr * 2] + __ldg(&bias[c0]);
                    v0 = v0 > 0.f ? v0 : slope * v0;
                }
                if (c0 + 1 < Nreal) {
                    v1 = acc[mt][nt][hr * 2 + 1] + __ldg(&bias[c0 + 1]);
                    v1 = v1 > 0.f ? v1 : slope * v1;
                }
                if (fp32_out) {
                    float2 o = make_float2(v0, v1);
                    *reinterpret_cast<float2*>(&((float*)Cv)[(size_t)r * ldc + c0]) = o;
                } else {
                    *reinterpret_cast<__half2*>(&((__half*)Cv)[(size_t)r * ldc + c0])
                        = __floats2half2_rn(v0, v1);
                }
            }
        }
    }
}

// ---------------- weight transpose + fp16 convert: dst[n][k] = src[k][n] ----------------
__global__ void k_round_th(const float* __restrict__ src, __half* __restrict__ dst,
                           int Ktrue, int Ntrue, int Kp, int total)
{
    int i = blockIdx.x * blockDim.x + threadIdx.x;
    if (i >= total) return;
    int n = i / Kp, k = i - n * Kp;
    float v = 0.f;
    if (n < Ntrue && k < Ktrue) v = src[(size_t)k * Ntrue + n];
    dst[i] = __float2half_rn(v);
}

__global__ void k_zero(float* p, int n)
{
    int i = blockIdx.x * blockDim.x + threadIdx.x;
    if (i < n) p[i] = 0.f;
}

__global__ void k_f2h(const float* __restrict__ src, __half* __restrict__ dst, int n)
{
    int i = blockIdx.x * blockDim.x + threadIdx.x;
    if (i < n) dst[i] = __float2half_rn(src[i]);
}

// ---------------- fp32 tiled GEMM with split-K (mic/dis feature GEMMs) ----------------
#define BM 128
#define BN 128
#define BKK 8
#define TM 8
#define TN 8

__global__ void __launch_bounds__(256, 2)
sgemm(const float* __restrict__ A, const float* __restrict__ B,
      const float* __restrict__ bias, float* __restrict__ C,
      int M, int N, int K, int act, float slope)
{
    __shared__ float As[BKK][BM];
    __shared__ float Bs[BKK][BN];

    const int tid = threadIdx.x;
    const int m0 = blockIdx.y * BM;
    const int n0 = blockIdx.x * BN;

    int chunk = (K + gridDim.z - 1) / gridDim.z;
    int kb = blockIdx.z * chunk;
    int ke = min(K, kb + chunk);

    const int arow = tid >> 1;
    const int acol = (tid & 1) * 4;
    const int brow = tid >> 5;
    const int bcol = (tid & 31) * 4;
    const int tr = (tid >> 4) * TM;
    const int tc = (tid & 15) * TN;

    float acc[TM][TN];
#pragma unroll
    for (int i = 0; i < TM; i++)
#pragma unroll
        for (int j = 0; j < TN; j++) acc[i][j] = 0.f;

    for (int k0 = kb; k0 < ke; k0 += BKK) {
#pragma unroll
        for (int j = 0; j < 4; j++) {
            int k = k0 + acol + j;
            int mm = m0 + arow;
            As[acol + j][arow] = (mm < M && k < ke) ? A[(size_t)mm * K + k] : 0.f;
        }
#pragma unroll
        for (int j = 0; j < 4; j++) {
            int k = k0 + brow;
            int n = n0 + bcol + j;
            Bs[brow][bcol + j] = (k < ke && n < N) ? B[(size_t)k * N + n] : 0.f;
        }
        __syncthreads();
#pragma unroll
        for (int kk = 0; kk < BKK; kk++) {
            float ra[TM], rb[TN];
#pragma unroll
            for (int i = 0; i < TM; i++) ra[i] = As[kk][tr + i];
#pragma unroll
            for (int j = 0; j < TN; j++) rb[j] = Bs[kk][tc + j];
#pragma unroll
            for (int i = 0; i < TM; i++)
#pragma unroll
                for (int j = 0; j < TN; j++) acc[i][j] += ra[i] * rb[j];
        }
        __syncthreads();
    }

#pragma unroll
    for (int i = 0; i < TM; i++) {
        int mm = m0 + tr + i;
        if (mm >= M) continue;
#pragma unroll
        for (int j = 0; j < TN; j++) {
            int n = n0 + tc + j;
            if (n >= N) continue;
            float v = acc[i][j];
            if (act == 2) { atomicAdd(&C[(size_t)mm * N + n], v); continue; }
            if (bias) v += bias[n];
            if (act == 1) v = v > 0.f ? v : slope * v;
            C[(size_t)mm * N + n] = v;
        }
    }
}

// ---------------- GAT: edge logits ----------------
__global__ void k_edge_e(const int* __restrict__ ei, const float* __restrict__ att)
{
    int w = (blockIdx.x * blockDim.x + threadIdx.x) >> 5;
    int lane = threadIdx.x & 31;
    if (w >= ETOT) return;
    int s, d;
    if (w < EE) { s = ei[w]; d = ei[EE + w]; } else { s = d = w - EE; }
    const float* xls = g_xl + (size_t)s * HC;
    const float* xrd = g_xr + (size_t)d * HC;
#pragma unroll
    for (int h = 0; h < HH; h++) {
        float sum = 0.f;
#pragma unroll
        for (int c0 = 0; c0 < CC; c0 += 32) {
            int c = c0 + lane;
            float z = xls[h * CC + c] + xrd[h * CC + c];
            z = z > 0.f ? z : 0.2f * z;
            sum += z * __ldg(&att[h * CC + c]);
        }
#pragma unroll
        for (int o = 16; o; o >>= 1) sum += __shfl_down_sync(0xffffffffu, sum, o);
        if (lane == 0) g_e[w * HH + h] = sum;
    }
}

// ---------------- GAT: CSR build ----------------
__global__ void k_cnt()
{
    int i = blockIdx.x * blockDim.x + threadIdx.x;
    if (i < NN) g_cnt[i] = 1;                       // self loop
}
__global__ void k_cnt2(const int* __restrict__ ei)
{
    int i = blockIdx.x * blockDim.x + threadIdx.x;
    if (i < EE) atomicAdd(&g_cnt[ei[EE + i]], 1);
}
__global__ void k_scan()
{
    __shared__ int s[NN];
    int tid = threadIdx.x;
    for (int i = tid; i < NN; i += blockDim.x) s[i] = g_cnt[i];
    __syncthreads();
    if (tid == 0) {
        int run = 0;
        for (int i = 0; i < NN; i++) { int c = s[i]; s[i] = run; run += c; }
        g_off[NN] = run;
    }
    __syncthreads();
    for (int i = tid; i < NN; i += blockDim.x) { g_off[i] = s[i]; g_cnt[i] = s[i]; }
}
__global__ void k_scatter(const int* __restrict__ ei)
{
    int i = blockIdx.x * blockDim.x + threadIdx.x;
    if (i >= ETOT) return;
    int dst = (i < EE) ? ei[EE + i] : i - EE;
    int pos = atomicAdd(&g_cnt[dst], 1);
    g_sorted[pos] = i;
}

// ---------------- GAT: per-destination softmax + aggregate ----------------
#define ACH 128
__global__ void __launch_bounds__(256)
k_aggr2(const int* __restrict__ ei)
{
    const int d = blockIdx.x;
    const int tid = threadIdx.x;
    const int wid = tid >> 5, lane = tid & 31;
    const int beg = g_off[d], end = g_off[d + 1];
    const int nE = end - beg;

    __shared__ float ex_s[ACH][HH];
    __shared__ int   src_s[ACH];
    __shared__ unsigned mxu[HH];

    if (tid < HH) mxu[tid] = 0u;
    __syncthreads();

    for (int j = tid; j < nE * HH; j += 256) {
        int e = g_sorted[beg + (j >> 3)];
        atomicMax(&mxu[j & 7], fenc(g_e[e * HH + (j & 7)]));
    }
    __syncthreads();

    const int h = wid;
    const int cbase = h * CC + lane * 4;

    float a0 = 0.f, a1 = 0.f, a2 = 0.f, a3 = 0.f, denp = 0.f;

    for (int c0 = 0; c0 < nE; c0 += ACH) {
        int n = min(ACH, nE - c0);
        __syncthreads();
        for (int j = tid; j < n * HH; j += 256) {
            int ii = j >> 3, hh = j & 7;
            int e = g_sorted[beg + c0 + ii];
            ex_s[ii][hh] = __expf(g_e[e * HH + hh] - fdec(mxu[hh]));
        }
        for (int j = tid; j < n; j += 256) {
            int e = g_sorted[beg + c0 + j];
            src_s[j] = (e < EE) ? ei[e] : e - EE;
        }
        __syncthreads();
        for (int i = 0; i < n; i++) {
            float exv = ex_s[i][h];
            const float4 x = *reinterpret_cast<const float4*>(
                &g_xl[(size_t)src_s[i] * HC + cbase]);
            a0 += exv * x.x; a1 += exv * x.y; a2 += exv * x.z; a3 += exv * x.w;
        }
        for (int i = lane; i < n; i += 32) denp += ex_s[i][h];
    }
#pragma unroll
    for (int o = 16; o; o >>= 1) denp += __shfl_xor_sync(0xffffffffu, denp, o);
    float inv = 1.f / denp;
    float4 o4 = make_float4(a0 * inv, a1 * inv, a2 * inv, a3 * inv);
    *reinterpret_cast<float4*>(&g_gat[(size_t)d * HC + cbase]) = o4;
}

// ---------------- CNN ----------------
__global__ void k_conv(const float* __restrict__ gbias,
                       const float* __restrict__ cw1,  const float* __restrict__ cb1,
                       const float* __restrict__ cw4,  const float* __restrict__ cb4,
                       const float* __restrict__ cw16, const float* __restrict__ cb16,
                       const float* __restrict__ cw32, const float* __restrict__ cb32,
                       float* __restrict__ cnn)
{
    __shared__ float row[HC];
    __shared__ float w1[48], w4[192], w16[768], w32[1536];
    __shared__ float b[24];
    int n = blockIdx.x, tid = threadIdx.x;
    for (int i = tid; i < HC; i += blockDim.x)
        row[i] = g_gat[(size_t)n * HC + i] + gbias[i];
    for (int i = tid; i < 48;   i += blockDim.x) w1[i]  = cw1[i];
    for (int i = tid; i < 192;  i += blockDim.x) w4[i]  = cw4[i];
    for (int i = tid; i < 768;  i += blockDim.x) w16[i] = cw16[i];
    for (int i = tid; i < 1536; i += blockDim.x) w32[i] = cw32[i];
    if (tid < 6) { b[tid] = cb1[tid]; b[6+tid] = cb4[tid]; b[12+tid] = cb16[tid]; b[18+tid] = cb32[tid]; }
    __syncthreads();

    float* orow = cnn + (size_t)n * FDIM;
    for (int i = tid; i < FDIM; i += blockDim.x) {
        const float* w; int kw, o, x0, bb, j;
        if (i < 768)       { j = i;        kw = 1;  w = w1;  o = j / 128; x0 = j % 128; bb = 0;  }
        else if (i < 1518) { j = i - 768;  kw = 4;  w = w4;  o = j / 125; x0 = j % 125; bb = 6;  }
        else if (i < 2196) { j = i - 1518; kw = 16; w = w16; o = j / 113; x0 = j % 113; bb = 12; }
        else               { j = i - 2196; kw = 32; w = w32; o = j / 97;  x0 = j % 97;  bb = 18; }
        float s = b[bb + o];
        const float* wo = w + o * 8 * kw;
        for (int kh = 0; kh < 8; kh++)
            for (int x = 0; x < kw; x++)
                s += row[kh * 128 + x0 + x] * wo[kh * kw + x];
        orow[i] = s > 0.f ? s : 0.f;
    }
}

// ---------------- pair features ----------------
__global__ void k_feats(const int* __restrict__ pos, const int* __restrict__ neg,
                        const float* __restrict__ cnn)
{
    int p = blockIdx.x;
    int mi, di;
    if (p < PP) { mi = pos[p * 2]; di = pos[p * 2 + 1]; }
    else        { mi = neg[(p - PP) * 2]; di = neg[(p - PP) * 2 + 1]; }
    const float* a  = cnn + (size_t)mi * FDIM;
    const float* bb = cnn + (size_t)(NM + di) * FDIM;
    __half2* f = reinterpret_cast<__half2*>(g_featsh + (size_t)p * FPAD);
    for (int i = threadIdx.x; i < FPAD / 2; i += blockDim.x) {
        int c = i * 2;
        float v0 = (c     < FDIM) ? a[c]     * bb[c]     : 0.f;
        float v1 = (c + 1 < FDIM) ? a[c + 1] * bb[c + 1] : 0.f;
        f[i] = __floats2half2_rn(v0, v1);
    }
}

// ---------------- final GEMV + sigmoid + labels ----------------
__global__ void k_final(const float* __restrict__ mw4, float* __restrict__ out,
                        int write_labels)
{
    int w = (blockIdx.x * blockDim.x + threadIdx.x) >> 5;
    int lane = threadIdx.x & 31;
    if (w >= NPAIR) return;
    const __half* hrow = g_h3h + (size_t)w * D3P;
    float s = 0.f;
    for (int k = lane; k < D3; k += 32) s += __half2float(hrow[k]) * mw4[k];
#pragma unroll
    for (int o = 16; o; o >>= 1) s += __shfl_down_sync(0xffffffffu, s, o);
    if (lane == 0) {
        out[w] = 1.f / (1.f + expf(-s));
        if (write_labels) out[NPAIR + w] = (w < PP) ? 1.f : 0.f;
    }
}

// ---------------- launcher ----------------
static inline int cdiv(int a, int b) { return (a + b - 1) / b; }

extern "C" void kernel_launch(void* const* d_in, const int* in_sizes, int n_in,
                              void* d_out, int out_size)
{
    const float* mic   = (const float*)d_in[0];
    const float* dis   = (const float*)d_in[1];
    const int*   ei    = (const int*)  d_in[2];
    const int*   pos   = (const int*)  d_in[3];
    const int*   neg   = (const int*)  d_in[4];
    const float* W_mic = (const float*)d_in[6];
    const float* W_dis = (const float*)d_in[7];
    const float* Wl    = (const float*)d_in[8];
    const float* bl    = (const float*)d_in[9];
    const float* Wr    = (const float*)d_in[10];
    const float* br    = (const float*)d_in[11];
    const float* att   = (const float*)d_in[12];
    const float* gbias = (const float*)d_in[13];
    const float* cw1   = (const float*)d_in[14];
    const float* cb1   = (const float*)d_in[15];
    const float* cw4   = (const float*)d_in[16];
    const float* cb4   = (const float*)d_in[17];
    const float* cw16  = (const float*)d_in[18];
    const float* cb16  = (const float*)d_in[19];
    const float* cw32  = (const float*)d_in[20];
    const float* cb32  = (const float*)d_in[21];
    const float* mw1   = (const float*)d_in[22];
    const float* mb1   = (const float*)d_in[23];
    const float* mw2   = (const float*)d_in[24];
    const float* mb2   = (const float*)d_in[25];
    const float* mw3   = (const float*)d_in[26];
    const float* mb3   = (const float*)d_in[27];
    const float* mw4   = (const float*)d_in[28];
    float* out = (float*)d_out;

    float *p_h, *p_xl, *p_xr, *p_cnn;
    __half *p_hh, *p_feats, *p_h1, *p_h2, *p_h3;
    __half *p_w1t, *p_w2t, *p_w3t, *p_wlt, *p_wrt;
    cudaGetSymbolAddress((void**)&p_h,     g_h);
    cudaGetSymbolAddress((void**)&p_hh,    g_hh);
    cudaGetSymbolAddress((void**)&p_xl,    g_xl);
    cudaGetSymbolAddress((void**)&p_xr,    g_xr);
    cudaGetSymbolAddress((void**)&p_cnn,   g_cnn);
    cudaGetSymbolAddress((void**)&p_feats, g_featsh);
    cudaGetSymbolAddress((void**)&p_h1,    g_h1h);
    cudaGetSymbolAddress((void**)&p_h2,    g_h2h);
    cudaGetSymbolAddress((void**)&p_h3,    g_h3h);
    cudaGetSymbolAddress((void**)&p_w1t,   g_w1th);
    cudaGetSymbolAddress((void**)&p_w2t,   g_w2th);
    cudaGetSymbolAddress((void**)&p_w3t,   g_w3th);
    cudaGetSymbolAddress((void**)&p_wlt,   g_wlth);
    cudaGetSymbolAddress((void**)&p_wrt,   g_wrth);

    const int full = 2 * NPAIR + NN * FDIM;
    float* cnn = (out_size >= full) ? (out + 2 * NPAIR) : p_cnn;
    int write_labels = (out_size >= 2 * NPAIR) ? 1 : 0;

    cudaFuncSetAttribute(gemm_hc, cudaFuncAttributeMaxDynamicSharedMemorySize, SMEM_HC);

    dim3 blk(256);

    // weight transposes to fp16 (independent)
    k_round_th<<<cdiv(D1P * FPAD, 256), 256>>>(mw1, p_w1t, FDIM, D1, FPAD, D1P * FPAD);
    k_round_th<<<cdiv(D2NT * D1P, 256), 256>>>(mw2, p_w2t, D1, D2, D1P, D2NT * D1P);
    k_round_th<<<cdiv(D3NT * D2P, 256), 256>>>(mw3, p_w3t, D2, D3, D2P, D3NT * D2P);
    k_round_th<<<cdiv(HC * CC, 256), 256>>>(Wl, p_wlt, CC, HC, CC, HC * CC);
    k_round_th<<<cdiv(HC * CC, 256), 256>>>(Wr, p_wrt, CC, HC, CC, HC * CC);

    // CSR build (independent of features)
    k_cnt<<<cdiv(NN, 256), 256>>>();
    k_cnt2<<<cdiv(EE, 256), 256>>>(ei);
    k_scan<<<1, 256>>>();
    k_scatter<<<cdiv(ETOT, 256), 256>>>(ei);

    // h = concat(mic @ W_mic, dis @ W_dis)  (split-K + atomic add); rows 2300-2303 stay 0
    k_zero<<<cdiv(NNP * CC, 256), 256>>>(p_h, NNP * CC);
    sgemm<<<dim3(1, cdiv(NM, BM), 8), blk>>>(mic, W_mic, nullptr, p_h,           NM, CC, NM, 2, 0.f);
    sgemm<<<dim3(1, cdiv(ND, BM), 4), blk>>>(dis, W_dis, nullptr, p_h + NM * CC, ND, CC, ND, 2, 0.f);
    k_f2h<<<cdiv(NNP * CC, 256), 256>>>(p_h, p_hh, NNP * CC);

    // xl / xr via fp16 tensor GEMM (identity activation via slope=1)
    gemm_hc<<<dim3(HC / 128, NNP / 128), blk, SMEM_HC>>>(p_hh, p_wlt, bl, p_xl, HC, CC, HC, 1.0f, 1);
    gemm_hc<<<dim3(HC / 128, NNP / 128), blk, SMEM_HC>>>(p_hh, p_wrt, br, p_xr, HC, CC, HC, 1.0f, 1);

    // GAT attention
    k_edge_e<<<cdiv(ETOT * 32, 256), 256>>>(ei, att);
    k_aggr2<<<NN, 256>>>(ei);

    // CNN embeddings
    k_conv<<<NN, 256>>>(gbias, cw1, cb1, cw4, cb4, cw16, cb16, cw32, cb32, cnn);

    // pair features + fp16 tensor-core MLP
    k_feats<<<NPAIR, 256>>>(pos, neg, cnn);
    gemm_hc<<<dim3(D1P / 128, NPAIR / 128), blk, SMEM_HC>>>(p_feats, p_w1t, mb1, p_h1, D1, FPAD, D1P, 0.01f, 0);
    gemm_hc<<<dim3(D2NT / 128, NPAIR / 128), blk, SMEM_HC>>>(p_h1, p_w2t, mb2, p_h2, D2, D1P, D2P, 0.01f, 0);
    gemm_hc<<<dim3(D3NT / 128, NPAIR / 128), blk, SMEM_HC>>>(p_h2, p_w3t, mb3, p_h3, D3, D2P, D3P, 0.01f, 0);
    k_final<<<cdiv(NPAIR * 32, 256), 256>>>(mw4, out, write_labels);
}

// round 8
// speedup vs baseline: 8.2124x; 1.0054x over previous
#include <cuda_runtime.h>
#include <cuda_fp16.h>
#include <cstdint>

// ---------------- problem dimensions ----------------
#define NM    1500
#define ND    800
#define NN    2300
#define NNP   2304          // NN padded to mult of 128
#define CC    128
#define HH    8
#define HC    1024
#define EE    80000
#define ETOT  (EE + NN)
#define PP    40000
#define NPAIR 80000
#define FDIM  2778
#define FPAD  2816          // mult of 64
#define D1    1389
#define D1P   1408
#define D2    694
#define D2P   704
#define D2NT  768
#define D3    463
#define D3P   464
#define D3NT  512

// ---------------- scratch ----------------
__device__ float    g_h    [NNP * CC];
__device__ __half   g_hh   [NNP * CC];
__device__ float    g_xl   [NNP * HC];
__device__ float    g_xr   [NNP * HC];
__device__ float    g_e    [ETOT * HH];     // overflow spill only
__device__ float    g_gat  [NN * HC];
__device__ float    g_cnn  [NN * FDIM];
__device__ int      g_cnt  [NN];
__device__ int      g_off  [NN + 1];
__device__ int      g_sorted[ETOT];
__device__ __half   g_featsh[(size_t)NPAIR * FPAD];
__device__ __half   g_h1h  [(size_t)NPAIR * D1P];
__device__ __half   g_h2h  [(size_t)NPAIR * D2P];
__device__ __half   g_h3h  [(size_t)NPAIR * D3P];
__device__ __half   g_w1th [(size_t)D1P  * FPAD];
__device__ __half   g_w2th [(size_t)D2NT * D1P];
__device__ __half   g_w3th [(size_t)D3NT * D2P];
__device__ __half   g_wlth [HC * CC];
__device__ __half   g_wrth [HC * CC];

// ---------------- helpers ----------------
__device__ __forceinline__ unsigned fenc(float f) {
    unsigned u = __float_as_uint(f);
    return (u & 0x80000000u) ? ~u : (u | 0x80000000u);
}
__device__ __forceinline__ float fdec(unsigned u) {
    unsigned v = (u & 0x80000000u) ? (u ^ 0x80000000u) : ~u;
    return __uint_as_float(v);
}

// ---------------- fp16 mma.sync GEMM, BK=64, 2-stage, occ 2 ----------------
#define HROWB 72
#define HTILE2 (128 * HROWB * 2)      // 18432 B
#define HSTG2  (2 * HTILE2)           // 36864 B
#define SMEM_HC (2 * HSTG2)           // 73728 B

#define LDSM_X4(r0, r1, r2, r3, addr) \
    asm volatile("ldmatrix.sync.aligned.m8n8.x4.shared.b16 {%0,%1,%2,%3}, [%4];" \
        : "=r"(r0), "=r"(r1), "=r"(r2), "=r"(r3) : "r"(addr))

__global__ void __launch_bounds__(256, 2)
gemm_hc(const __half* __restrict__ A, const __half* __restrict__ Bt,
        const float* __restrict__ bias, void* __restrict__ Cv,
        int Nreal, int Kp, int ldc, float slope, int fp32_out)
{
    extern __shared__ __half sm[];
    const int tid  = threadIdx.x;
    const int lane = tid & 31, wid = tid >> 5;
    const int g = lane >> 2, tg = lane & 3;
    const int wm = wid & 1, wn = wid >> 1;
    const int m0 = blockIdx.y * 128, n0 = blockIdx.x * 128;
    const unsigned smb = (unsigned)__cvta_generic_to_shared(sm);

    float acc[4][4][4];
#pragma unroll
    for (int a = 0; a < 4; a++)
#pragma unroll
        for (int b = 0; b < 4; b++)
#pragma unroll
            for (int c = 0; c < 4; c++) acc[a][b][c] = 0.f;

    const unsigned a_off = (unsigned)(((lane & 15) * HROWB + (lane >> 4) * 8) * 2);
    const unsigned b_off = (unsigned)(((((lane >> 4) << 3) + (lane & 7)) * HROWB
                                      + ((lane >> 3) & 1) * 8) * 2);

    auto fill = [&](int s, int kt) {
        unsigned ab = smb + (unsigned)s * HSTG2;
        unsigned bb = ab + HTILE2;
#pragma unroll
        for (int p = 0; p < 4; p++) {
            int i = p * 256 + tid;
            int row = i >> 3, c = i & 7;
            unsigned off = (unsigned)((row * HROWB + c * 8) * 2);
            const __half* srcA = A  + (size_t)(m0 + row) * Kp + kt + c * 8;
            const __half* srcB = Bt + (size_t)(n0 + row) * Kp + kt + c * 8;
            asm volatile("cp.async.cg.shared.global [%0], [%1], 16;" :: "r"(ab + off), "l"(srcA));
            asm volatile("cp.async.cg.shared.global [%0], [%1], 16;" :: "r"(bb + off), "l"(srcB));
        }
        asm volatile("cp.async.commit_group;" ::: "memory");
    };

    const int T = Kp >> 6;
    fill(0, 0);
    if (T > 1) fill(1, 64);

    for (int t = 0; t < T; ++t) {
        if (t < T - 1) asm volatile("cp.async.wait_group 1;" ::: "memory");
        else           asm volatile("cp.async.wait_group 0;" ::: "memory");
        __syncthreads();

        unsigned ab = smb + (unsigned)(t & 1) * HSTG2;
        unsigned bb = ab + HTILE2;
#pragma unroll
        for (int kk = 0; kk < 4; ++kk) {
            const unsigned kb = (unsigned)(kk * 32);
            unsigned a[4][4], b[2][4];
#pragma unroll
            for (int mt = 0; mt < 4; ++mt) {
                unsigned ad = ab + (unsigned)((wm * 64 + mt * 16) * HROWB * 2) + a_off + kb;
                LDSM_X4(a[mt][0], a[mt][1], a[mt][2], a[mt][3], ad);
            }
#pragma unroll
            for (int np = 0; np < 2; ++np) {
                unsigned bd = bb + (unsigned)((wn * 32 + np * 16) * HROWB * 2) + b_off + kb;
                LDSM_X4(b[np][0], b[np][1], b[np][2], b[np][3], bd);
            }
#pragma unroll
            for (int mt = 0; mt < 4; ++mt)
#pragma unroll
                for (int nt = 0; nt < 4; ++nt) {
                    unsigned b0 = b[nt >> 1][(nt & 1) * 2];
                    unsigned b1 = b[nt >> 1][(nt & 1) * 2 + 1];
                    asm volatile(
                        "mma.sync.aligned.m16n8k16.row.col.f32.f16.f16.f32 "
                        "{%0,%1,%2,%3}, {%4,%5,%6,%7}, {%8,%9}, {%0,%1,%2,%3};\n"
                        : "+f"(acc[mt][nt][0]), "+f"(acc[mt][nt][1]),
                          "+f"(acc[mt][nt][2]), "+f"(acc[mt][nt][3])
                        : "r"(a[mt][0]), "r"(a[mt][1]), "r"(a[mt][2]), "r"(a[mt][3]),
                          "r"(b0), "r"(b1));
                }
        }
        __syncthreads();
        if (t + 2 < T) fill(t & 1, (t + 2) * 64);
    }

#pragma unroll
    for (int mt = 0; mt < 4; ++mt) {
#pragma unroll
        for (int nt = 0; nt < 4; ++nt) {
            int r0 = m0 + wm * 64 + mt * 16 + g;
            int c0 = n0 + wn * 32 + nt * 8 + 2 * tg;
            if (c0 >= ldc) continue;
#pragma unroll
            for (int hr = 0; hr < 2; ++hr) {
                int r = r0 + hr * 8;
                float v0 = 0.f, v1 = 0.f;
                if (c0 < Nreal) {
                    v0 = acc[mt][nt][hr * 2] + __ldg(&bias[c0]);
                    v0 = v0 > 0.f ? v0 : slope * v0;
                }
                if (c0 + 1 < Nreal) {
                    v1 = acc[mt][nt][hr * 2 + 1] + __ldg(&bias[c0 + 1]);
                    v1 = v1 > 0.f ? v1 : slope * v1;
                }
                if (fp32_out) {
                    *reinterpret_cast<float2*>(&((float*)Cv)[(size_t)r * ldc + c0])
                        = make_float2(v0, v1);
                } else {
                    *reinterpret_cast<__half2*>(&((__half*)Cv)[(size_t)r * ldc + c0])
                        = __floats2half2_rn(v0, v1);
                }
            }
        }
    }
}

// ---------------- tiled transpose + fp16: dst[n][k] = src[k][n] ----------------
__global__ void k_transp(const float* __restrict__ src, __half* __restrict__ dst,
                         int Ktrue, int Ntrue, int Kp, int Npad)
{
    __shared__ float t[32][33];
    int k0 = blockIdx.x * 32, n0 = blockIdx.y * 32;
    int tx = threadIdx.x, ty = threadIdx.y;
#pragma unroll
    for (int i = 0; i < 4; i++) {
        int k = k0 + ty + i * 8, n = n0 + tx;
        t[ty + i * 8][tx] = (k < Ktrue && n < Ntrue) ? src[(size_t)k * Ntrue + n] : 0.f;
    }
    __syncthreads();
#pragma unroll
    for (int i = 0; i < 4; i++) {
        int n = n0 + ty + i * 8, k = k0 + tx;
        if (n < Npad && k < Kp)
            dst[(size_t)n * Kp + k] = __float2half_rn(t[tx][ty + i * 8]);
    }
}

__global__ void k_zero_init(float* p, int n)
{
    int i = blockIdx.x * blockDim.x + threadIdx.x;
    if (i < n) p[i] = 0.f;
    if (i < NN) g_cnt[i] = 1;                       // self loop counts
}

__global__ void k_f2h(const float* __restrict__ src, __half* __restrict__ dst, int n)
{
    int i = blockIdx.x * blockDim.x + threadIdx.x;
    if (i < n) dst[i] = __float2half_rn(src[i]);
}

// ---------------- fp32 tiled GEMM with split-K ----------------
#define BM 128
#define BN 128
#define BKK 8
#define TM 8
#define TN 8

__global__ void __launch_bounds__(256, 2)
sgemm(const float* __restrict__ A, const float* __restrict__ B,
      const float* __restrict__ bias, float* __restrict__ C,
      int M, int N, int K, int act, float slope)
{
    __shared__ float As[BKK][BM];
    __shared__ float Bs[BKK][BN];

    const int tid = threadIdx.x;
    const int m0 = blockIdx.y * BM;
    const int n0 = blockIdx.x * BN;

    int chunk = (K + gridDim.z - 1) / gridDim.z;
    int kb = blockIdx.z * chunk;
    int ke = min(K, kb + chunk);

    const int arow = tid >> 1;
    const int acol = (tid & 1) * 4;
    const int brow = tid >> 5;
    const int bcol = (tid & 31) * 4;
    const int tr = (tid >> 4) * TM;
    const int tc = (tid & 15) * TN;

    float acc[TM][TN];
#pragma unroll
    for (int i = 0; i < TM; i++)
#pragma unroll
        for (int j = 0; j < TN; j++) acc[i][j] = 0.f;

    for (int k0 = kb; k0 < ke; k0 += BKK) {
#pragma unroll
        for (int j = 0; j < 4; j++) {
            int k = k0 + acol + j;
            int mm = m0 + arow;
            As[acol + j][arow] = (mm < M && k < ke) ? A[(size_t)mm * K + k] : 0.f;
        }
#pragma unroll
        for (int j = 0; j < 4; j++) {
            int k = k0 + brow;
            int n = n0 + bcol + j;
            Bs[brow][bcol + j] = (k < ke && n < N) ? B[(size_t)k * N + n] : 0.f;
        }
        __syncthreads();
#pragma unroll
        for (int kk = 0; kk < BKK; kk++) {
            float ra[TM], rb[TN];
#pragma unroll
            for (int i = 0; i < TM; i++) ra[i] = As[kk][tr + i];
#pragma unroll
            for (int j = 0; j < TN; j++) rb[j] = Bs[kk][tc + j];
#pragma unroll
            for (int i = 0; i < TM; i++)
#pragma unroll
                for (int j = 0; j < TN; j++) acc[i][j] += ra[i] * rb[j];
        }
        __syncthreads();
    }

#pragma unroll
    for (int i = 0; i < TM; i++) {
        int mm = m0 + tr + i;
        if (mm >= M) continue;
#pragma unroll
        for (int j = 0; j < TN; j++) {
            int n = n0 + tc + j;
            if (n >= N) continue;
            float v = acc[i][j];
            if (act == 2) { atomicAdd(&C[(size_t)mm * N + n], v); continue; }
            if (bias) v += bias[n];
            if (act == 1) v = v > 0.f ? v : slope * v;
            C[(size_t)mm * N + n] = v;
        }
    }
}

// ---------------- GAT: CSR build ----------------
__global__ void k_cnt2(const int* __restrict__ ei)
{
    int i = blockIdx.x * blockDim.x + threadIdx.x;
    if (i < EE) atomicAdd(&g_cnt[ei[EE + i]], 1);
}
__global__ void k_scan()
{
    __shared__ int part[256];
    int tid = threadIdx.x;
    int base = tid * 9;
    int loc[9]; int s = 0;
#pragma unroll
    for (int i = 0; i < 9; i++) {
        int idx = base + i;
        int c = (idx < NN) ? g_cnt[idx] : 0;
        loc[i] = s; s += c;
    }
    part[tid] = s;
    __syncthreads();
    for (int o = 1; o < 256; o <<= 1) {
        int v = (tid >= o) ? part[tid - o] : 0;
        __syncthreads();
        part[tid] += v;
        __syncthreads();
    }
    int off = (tid > 0) ? part[tid - 1] : 0;
#pragma unroll
    for (int i = 0; i < 9; i++) {
        int idx = base + i;
        if (idx < NN) { g_off[idx] = off + loc[i]; g_cnt[idx] = off + loc[i]; }
    }
    if (tid == 255) g_off[NN] = part[255];
}
__global__ void k_scatter(const int* __restrict__ ei)
{
    int i = blockIdx.x * blockDim.x + threadIdx.x;
    if (i >= ETOT) return;
    int dst = (i < EE) ? ei[EE + i] : i - EE;
    int pos = atomicAdd(&g_cnt[dst], 1);
    g_sorted[pos] = i;
}

// ---------------- GAT fused: logits + softmax + aggregate ----------------
#define MAXE_S 512
__global__ void __launch_bounds__(256)
k_gat(const int* __restrict__ ei, const float* __restrict__ att)
{
    const int d = blockIdx.x;
    const int tid = threadIdx.x, wid = tid >> 5, lane = tid & 31;
    const int beg = g_off[d], nE = g_off[d + 1] - beg;

    __shared__ float xr_s[HC];
    __shared__ float att_s[HC];
    __shared__ float e_s[MAXE_S * HH];
    __shared__ int   src_all[MAXE_S];
    __shared__ unsigned mxu[HH];

    for (int i = tid; i < HC; i += 256) {
        xr_s[i]  = g_xr[(size_t)d * HC + i];
        att_s[i] = att[i];
    }
    if (tid < HH) mxu[tid] = 0u;
    __syncthreads();

    // pass 1: edge logits (one warp per edge, round-robin)
    for (int j = wid; j < nE; j += 8) {
        int e_idx = g_sorted[beg + j];
        int src = (e_idx < EE) ? ei[e_idx] : e_idx - EE;
        if (lane == 0 && j < MAXE_S) src_all[j] = src;
        const float* xlr = g_xl + (size_t)src * HC;
#pragma unroll
        for (int h = 0; h < HH; h++) {
            int c = h * CC + lane * 4;
            float4 xv = *reinterpret_cast<const float4*>(xlr + c);
            float4 rv = *reinterpret_cast<const float4*>(xr_s + c);
            float4 av = *reinterpret_cast<const float4*>(att_s + c);
            float z0 = xv.x + rv.x; z0 = z0 > 0.f ? z0 : 0.2f * z0;
            float z1 = xv.y + rv.y; z1 = z1 > 0.f ? z1 : 0.2f * z1;
            float z2 = xv.z + rv.z; z2 = z2 > 0.f ? z2 : 0.2f * z2;
            float z3 = xv.w + rv.w; z3 = z3 > 0.f ? z3 : 0.2f * z3;
            float s = z0 * av.x + z1 * av.y + z2 * av.z + z3 * av.w;
#pragma unroll
            for (int o = 16; o; o >>= 1) s += __shfl_down_sync(0xffffffffu, s, o);
            if (lane == 0) {
                if (j < MAXE_S) e_s[j * HH + h] = s;
                else            g_e[(size_t)(beg + j) * HH + h] = s;
                atomicMax(&mxu[h], fenc(s));
            }
        }
    }
    __syncthreads();

    // pass 2: warp = head; softmax-weighted aggregation
    const int h = wid;
    const float mxh = fdec(mxu[h]);
    const int cbase = h * CC + lane * 4;
    float a0 = 0.f, a1 = 0.f, a2 = 0.f, a3 = 0.f, den = 0.f;

    for (int j = 0; j < nE; j++) {
        float ev = (j < MAXE_S) ? e_s[j * HH + h] : g_e[(size_t)(beg + j) * HH + h];
        float ex = __expf(ev - mxh);
        den += ex;
        int src;
        if (j < MAXE_S) src = src_all[j];
        else {
            int e_idx = g_sorted[beg + j];
            src = (e_idx < EE) ? ei[e_idx] : e_idx - EE;
        }
        const float4 x = *reinterpret_cast<const float4*>(&g_xl[(size_t)src * HC + cbase]);
        a0 += ex * x.x; a1 += ex * x.y; a2 += ex * x.z; a3 += ex * x.w;
    }
    float inv = 1.f / den;
    *reinterpret_cast<float4*>(&g_gat[(size_t)d * HC + cbase])
        = make_float4(a0 * inv, a1 * inv, a2 * inv, a3 * inv);
}

// ---------------- CNN ----------------
__global__ void k_conv(const float* __restrict__ gbias,
                       const float* __restrict__ cw1,  const float* __restrict__ cb1,
                       const float* __restrict__ cw4,  const float* __restrict__ cb4,
                       const float* __restrict__ cw16, const float* __restrict__ cb16,
                       const float* __restrict__ cw32, const float* __restrict__ cb32,
                       float* __restrict__ cnn)
{
    __shared__ float row[HC];
    __shared__ float w1[48], w4[192], w16[768], w32[1536];
    __shared__ float b[24];
    int n = blockIdx.x, tid = threadIdx.x;
    for (int i = tid; i < HC; i += blockDim.x)
        row[i] = g_gat[(size_t)n * HC + i] + gbias[i];
    for (int i = tid; i < 48;   i += blockDim.x) w1[i]  = cw1[i];
    for (int i = tid; i < 192;  i += blockDim.x) w4[i]  = cw4[i];
    for (int i = tid; i < 768;  i += blockDim.x) w16[i] = cw16[i];
    for (int i = tid; i < 1536; i += blockDim.x) w32[i] = cw32[i];
    if (tid < 6) { b[tid] = cb1[tid]; b[6+tid] = cb4[tid]; b[12+tid] = cb16[tid]; b[18+tid] = cb32[tid]; }
    __syncthreads();

    float* orow = cnn + (size_t)n * FDIM;
    for (int i = tid; i < FDIM; i += blockDim.x) {
        const float* w; int kw, o, x0, bb, j;
        if (i < 768)       { j = i;        kw = 1;  w = w1;  o = j / 128; x0 = j % 128; bb = 0;  }
        else if (i < 1518) { j = i - 768;  kw = 4;  w = w4;  o = j / 125; x0 = j % 125; bb = 6;  }
        else if (i < 2196) { j = i - 1518; kw = 16; w = w16; o = j / 113; x0 = j % 113; bb = 12; }
        else               { j = i - 2196; kw = 32; w = w32; o = j / 97;  x0 = j % 97;  bb = 18; }
        float s = b[bb + o];
        const float* wo = w + o * 8 * kw;
        for (int kh = 0; kh < 8; kh++)
            for (int x = 0; x < kw; x++)
                s += row[kh * 128 + x0 + x] * wo[kh * kw + x];
        orow[i] = s > 0.f ? s : 0.f;
    }
}

// ---------------- pair features (vectorized) ----------------
__global__ void k_feats(const int* __restrict__ pos, const int* __restrict__ neg,
                        const float* __restrict__ cnn)
{
    int p = blockIdx.x;
    int mi, di;
    if (p < PP) { mi = pos[p * 2]; di = pos[p * 2 + 1]; }
    else        { mi = neg[(p - PP) * 2]; di = neg[(p - PP) * 2 + 1]; }
    const float2* a = reinterpret_cast<const float2*>(cnn + (size_t)mi * FDIM);
    const float2* b = reinterpret_cast<const float2*>(cnn + (size_t)(NM + di) * FDIM);
    __half2* f = reinterpret_cast<__half2*>(g_featsh + (size_t)p * FPAD);
    for (int i = threadIdx.x; i < FPAD / 2; i += blockDim.x) {
        float v0 = 0.f, v1 = 0.f;
        if (i < FDIM / 2) {
            float2 av = a[i], bv = b[i];
            v0 = av.x * bv.x; v1 = av.y * bv.y;
        }
        f[i] = __floats2half2_rn(v0, v1);
    }
}

// ---------------- final GEMV + sigmoid + labels ----------------
__global__ void k_final(const float* __restrict__ mw4, float* __restrict__ out,
                        int write_labels)
{
    int w = (blockIdx.x * blockDim.x + threadIdx.x) >> 5;
    int lane = threadIdx.x & 31;
    if (w >= NPAIR) return;
    const __half* hrow = g_h3h + (size_t)w * D3P;
    float s = 0.f;
    for (int k = lane; k < D3; k += 32) s += __half2float(hrow[k]) * mw4[k];
#pragma unroll
    for (int o = 16; o; o >>= 1) s += __shfl_down_sync(0xffffffffu, s, o);
    if (lane == 0) {
        out[w] = 1.f / (1.f + expf(-s));
        if (write_labels) out[NPAIR + w] = (w < PP) ? 1.f : 0.f;
    }
}

// ---------------- launcher ----------------
static inline int cdiv(int a, int b) { return (a + b - 1) / b; }

extern "C" void kernel_launch(void* const* d_in, const int* in_sizes, int n_in,
                              void* d_out, int out_size)
{
    const float* mic   = (const float*)d_in[0];
    const float* dis   = (const float*)d_in[1];
    const int*   ei    = (const int*)  d_in[2];
    const int*   pos   = (const int*)  d_in[3];
    const int*   neg   = (const int*)  d_in[4];
    const float* W_mic = (const float*)d_in[6];
    const float* W_dis = (const float*)d_in[7];
    const float* Wl    = (const float*)d_in[8];
    const float* bl    = (const float*)d_in[9];
    const float* Wr    = (const float*)d_in[10];
    const float* br    = (const float*)d_in[11];
    const float* att   = (const float*)d_in[12];
    const float* gbias = (const float*)d_in[13];
    const float* cw1   = (const float*)d_in[14];
    const float* cb1   = (const float*)d_in[15];
    const float* cw4   = (const float*)d_in[16];
    const float* cb4   = (const float*)d_in[17];
    const float* cw16  = (const float*)d_in[18];
    const float* cb16  = (const float*)d_in[19];
    const float* cw32  = (const float*)d_in[20];
    const float* cb32  = (const float*)d_in[21];
    const float* mw1   = (const float*)d_in[22];
    const float* mb1   = (const float*)d_in[23];
    const float* mw2   = (const float*)d_in[24];
    const float* mb2   = (const float*)d_in[25];
    const float* mw3   = (const float*)d_in[26];
    const float* mb3   = (const float*)d_in[27];
    const float* mw4   = (const float*)d_in[28];
    float* out = (float*)d_out;

    float *p_h, *p_xl, *p_xr, *p_cnn;
    __half *p_hh, *p_feats, *p_h1, *p_h2, *p_h3;
    __half *p_w1t, *p_w2t, *p_w3t, *p_wlt, *p_wrt;
    cudaGetSymbolAddress((void**)&p_h,     g_h);
    cudaGetSymbolAddress((void**)&p_hh,    g_hh);
    cudaGetSymbolAddress((void**)&p_xl,    g_xl);
    cudaGetSymbolAddress((void**)&p_xr,    g_xr);
    cudaGetSymbolAddress((void**)&p_cnn,   g_cnn);
    cudaGetSymbolAddress((void**)&p_feats, g_featsh);
    cudaGetSymbolAddress((void**)&p_h1,    g_h1h);
    cudaGetSymbolAddress((void**)&p_h2,    g_h2h);
    cudaGetSymbolAddress((void**)&p_h3,    g_h3h);
    cudaGetSymbolAddress((void**)&p_w1t,   g_w1th);
    cudaGetSymbolAddress((void**)&p_w2t,   g_w2th);
    cudaGetSymbolAddress((void**)&p_w3t,   g_w3th);
    cudaGetSymbolAddress((void**)&p_wlt,   g_wlth);
    cudaGetSymbolAddress((void**)&p_wrt,   g_wrth);

    const int full = 2 * NPAIR + NN * FDIM;
    float* cnn = (out_size >= full) ? (out + 2 * NPAIR) : p_cnn;
    int write_labels = (out_size >= 2 * NPAIR) ? 1 : 0;

    cudaFuncSetAttribute(gemm_hc, cudaFuncAttributeMaxDynamicSharedMemorySize, SMEM_HC);

    dim3 blk(256);
    dim3 tblk(32, 8);

    // tiled weight transposes to fp16
    k_transp<<<dim3(CC / 32, HC / 32), tblk>>>(Wl, p_wlt, CC, HC, CC, HC);
    k_transp<<<dim3(CC / 32, HC / 32), tblk>>>(Wr, p_wrt, CC, HC, CC, HC);
    k_transp<<<dim3(FPAD / 32, D1P / 32), tblk>>>(mw1, p_w1t, FDIM, D1, FPAD, D1P);
    k_transp<<<dim3(D1P / 32, D2NT / 32), tblk>>>(mw2, p_w2t, D1, D2, D1P, D2NT);
    k_transp<<<dim3(D2P / 32, D3NT / 32), tblk>>>(mw3, p_w3t, D2, D3, D2P, D3NT);

    // h scratch zero + CSR count init (fused)
    k_zero_init<<<cdiv(NNP * CC, 256), 256>>>(p_h, NNP * CC);
    k_cnt2<<<cdiv(EE, 256), 256>>>(ei);
    k_scan<<<1, 256>>>();
    k_scatter<<<cdiv(ETOT, 256), 256>>>(ei);

    // h = concat(mic @ W_mic, dis @ W_dis)  (split-K + atomic add)
    sgemm<<<dim3(1, cdiv(NM, BM), 8), blk>>>(mic, W_mic, nullptr, p_h,           NM, CC, NM, 2, 0.f);
    sgemm<<<dim3(1, cdiv(ND, BM), 4), blk>>>(dis, W_dis, nullptr, p_h + NM * CC, ND, CC, ND, 2, 0.f);
    k_f2h<<<cdiv(NNP * CC, 256), 256>>>(p_h, p_hh, NNP * CC);

    // xl / xr via fp16 tensor GEMM (identity activation via slope=1)
    gemm_hc<<<dim3(HC / 128, NNP / 128), blk, SMEM_HC>>>(p_hh, p_wlt, bl, p_xl, HC, CC, HC, 1.0f, 1);
    gemm_hc<<<dim3(HC / 128, NNP / 128), blk, SMEM_HC>>>(p_hh, p_wrt, br, p_xr, HC, CC, HC, 1.0f, 1);

    // fused GAT (logits + softmax + aggregation)
    k_gat<<<NN, 256>>>(ei, att);

    // CNN embeddings
    k_conv<<<NN, 256>>>(gbias, cw1, cb1, cw4, cb4, cw16, cb16, cw32, cb32, cnn);

    // pair features + fp16 tensor-core MLP
    k_feats<<<NPAIR, 256>>>(pos, neg, cnn);
    gemm_hc<<<dim3(D1P / 128, NPAIR / 128), blk, SMEM_HC>>>(p_feats, p_w1t, mb1, p_h1, D1, FPAD, D1P, 0.01f, 0);
    gemm_hc<<<dim3(D2NT / 128, NPAIR / 128), blk, SMEM_HC>>>(p_h1, p_w2t, mb2, p_h2, D2, D1P, D2P, 0.01f, 0);
    gemm_hc<<<dim3(D3NT / 128, NPAIR / 128), blk, SMEM_HC>>>(p_h2, p_w3t, mb3, p_h3, D3, D2P, D3P, 0.01f, 0);
    k_final<<<cdiv(NPAIR * 32, 256), 256>>>(mw4, out, write_labels);
}